// round 9
// baseline (speedup 1.0000x reference)
#include <cuda_runtime.h>
#include <cuda_bf16.h>
#include <cuda_fp16.h>
#include <math.h>
#include <stdint.h>

#define NEMB 20000
#define DEMB 128
#define NA   8192
#define PDIM 10000
#define FEPS 1e-8f
#define HS_SCALE 64.0f

// ---------------- scratch (device globals; no allocation allowed) ----------
__device__ float    g_sims_o[NA];
__device__ float    g_sims_n[NA];
__device__ unsigned g_mkey_o[NEMB];
__device__ unsigned g_mkey_n[NEMB];
__device__ float    g_ssum_o[NEMB];
__device__ float    g_ssum_n[NEMB];
__device__ float    g_cnt[NEMB];
__device__ float    g_dinv[NA];
__device__ float    g_Lu, g_LpNum, g_LpDen, g_Lc;
__device__ int      g_mask_mode;   // 0 = byte(bool), 1 = int32, 2 = float32

// W = e4m3(A * mask) (64 MB), Ht8[d][j] = e4m3(HS_SCALE * dinv_j * H[j][d]) (1 MB)
__device__ unsigned char g_W8[(size_t)NA * NA];
__device__ unsigned char g_Ht8[(size_t)DEMB * NA];

// ---------------- helpers ---------------------------------------------------
__device__ __forceinline__ unsigned fkey(float f) {
    unsigned u = __float_as_uint(f);
    return (u & 0x80000000u) ? ~u : (u | 0x80000000u);
}
__device__ __forceinline__ float fkey_inv(unsigned k) {
    return (k & 0x80000000u) ? __uint_as_float(k & 0x7fffffffu)
                             : __uint_as_float(~k);
}
__device__ __forceinline__ float4 mask4(const void* m, int mode, int idx4) {
    float4 r;
    if (mode == 0) {                       // packed bytes (bool)
        unsigned w = __ldcs(&((const unsigned*)m)[idx4]);
        r.x = (w & 0x000000ffu) ? 1.f : 0.f;
        r.y = (w & 0x0000ff00u) ? 1.f : 0.f;
        r.z = (w & 0x00ff0000u) ? 1.f : 0.f;
        r.w = (w & 0xff000000u) ? 1.f : 0.f;
    } else if (mode == 1) {                // int32 0/1
        int4 v = __ldcs(&((const int4*)m)[idx4]);
        r.x = v.x ? 1.f : 0.f; r.y = v.y ? 1.f : 0.f;
        r.z = v.z ? 1.f : 0.f; r.w = v.w ? 1.f : 0.f;
    } else {                               // float32
        r = __ldcs(&((const float4*)m)[idx4]);
    }
    return r;
}
__device__ __forceinline__ float softplusf(float x) {
    return fmaxf(x, 0.f) + log1pf(expf(-fabsf(x)));
}
__device__ __forceinline__ uint32_t s2u(const void* p) {
    uint32_t a;
    asm("{ .reg .u64 t; cvta.to.shared.u64 t, %1; cvt.u32.u64 %0, t; }"
        : "=r"(a) : "l"(p));
    return a;
}
__device__ __forceinline__ void cp16(uint32_t dst, const void* src) {
    asm volatile("cp.async.cg.shared.global [%0], [%1], 16;\n"
                 :: "r"(dst), "l"(src) : "memory");
}
#define CP_COMMIT() asm volatile("cp.async.commit_group;" ::: "memory")
#define CP_WAIT2()  asm volatile("cp.async.wait_group 2;" ::: "memory")

__device__ __forceinline__ void ldsm4(uint32_t* r, uint32_t addr) {
    asm volatile("ldmatrix.sync.aligned.m8n8.x4.shared.b16 {%0,%1,%2,%3}, [%4];"
                 : "=r"(r[0]), "=r"(r[1]), "=r"(r[2]), "=r"(r[3]) : "r"(addr));
}
// fp8 e4m3 mma, k32
__device__ __forceinline__ void mma16832f8(float* c, const uint32_t* a, const uint32_t* b) {
    asm volatile(
        "mma.sync.aligned.m16n8k32.row.col.f32.e4m3.e4m3.f32 "
        "{%0,%1,%2,%3}, {%4,%5,%6,%7}, {%8,%9}, {%0,%1,%2,%3};"
        : "+f"(c[0]), "+f"(c[1]), "+f"(c[2]), "+f"(c[3])
        : "r"(a[0]), "r"(a[1]), "r"(a[2]), "r"(a[3]), "r"(b[0]), "r"(b[1]));
}
// pack 4 floats -> 4 e4m3 bytes (x0 at lowest byte)
__device__ __forceinline__ uint32_t e4m3x4(float x0, float x1, float x2, float x3) {
    uint16_t lo, hi;
    asm("cvt.rn.satfinite.e4m3x2.f32 %0, %1, %2;" : "=h"(lo) : "f"(x1), "f"(x0));
    asm("cvt.rn.satfinite.e4m3x2.f32 %0, %1, %2;" : "=h"(hi) : "f"(x3), "f"(x2));
    return (uint32_t)lo | ((uint32_t)hi << 16);
}

// ---------------- K1: init + mask dtype detection ---------------------------
__global__ void init_kernel(const unsigned* __restrict__ m) {
    int i = blockIdx.x * blockDim.x + threadIdx.x;
    if (i < NEMB) {
        g_mkey_o[i] = 0u; g_mkey_n[i] = 0u;
        g_ssum_o[i] = 0.f; g_ssum_n[i] = 0.f;
        g_cnt[i] = 0.f;
    }
    if (i == 0) { g_Lu = 0.f; g_LpNum = 0.f; g_LpDen = 0.f; g_Lc = 0.f; }
    if (blockIdx.x == 0 && threadIdx.x < 32) {
        int vi = 0, vf = 0, vb = 0;
        for (int k = threadIdx.x; k < 256; k += 32) {
            unsigned w = m[k];
            if (w == 1u) vi++;
            else if (w == 0x3f800000u) vf++;
            else if (w != 0u) vb++;
        }
#pragma unroll
        for (int o = 16; o; o >>= 1) {
            vi += __shfl_xor_sync(~0u, vi, o);
            vf += __shfl_xor_sync(~0u, vf, o);
            vb += __shfl_xor_sync(~0u, vb, o);
        }
        if (threadIdx.x == 0) {
            int mode;
            if (vb >= vi && vb >= vf) mode = 0;
            else if (vi >= vf)        mode = 1;
            else                      mode = 2;
            g_mask_mode = mode;
        }
    }
}

// ---------------- K2 pieces -------------------------------------------------
__device__ __forceinline__ void deg_cvt_block(int row, const float4* __restrict__ A4,
                                              const void* __restrict__ mask) {
    int mode = g_mask_mode;
    int base4 = row * (NA / 4);
    unsigned* __restrict__ W4 = (unsigned*)g_W8;    // 4 fp8 per unsigned
    float s = 0.f;
#pragma unroll 4
    for (int c = threadIdx.x; c < NA / 4; c += 256) {
        float4 a = __ldcs(&A4[base4 + c]);
        float4 m = mask4(mask, mode, base4 + c);
        float x0 = a.x * m.x, x1 = a.y * m.y, x2 = a.z * m.z, x3 = a.w * m.w;
        s += (x0 + x1) + (x2 + x3);
        W4[base4 + c] = e4m3x4(x0, x1, x2, x3);
    }
    __shared__ float red[8];
#pragma unroll
    for (int o = 16; o; o >>= 1) s += __shfl_xor_sync(~0u, s, o);
    if ((threadIdx.x & 31) == 0) red[threadIdx.x >> 5] = s;
    __syncthreads();
    if (threadIdx.x < 8) {
        float v = red[threadIdx.x];
#pragma unroll
        for (int o = 4; o; o >>= 1) v += __shfl_xor_sync(0xffu, v, o);
        if (threadIdx.x == 0) g_dinv[row] = rsqrtf(v + FEPS);
    }
}

__device__ __forceinline__ void lu_block(int blk, const float* __restrict__ pred,
                                         const int* __restrict__ edges, int nE) {
    int e = blk * 256 + threadIdx.x;
    if (e >= nE) return;
    int u = edges[2 * e], v = edges[2 * e + 1];
    float s = __ldg(&pred[(long long)u * PDIM + v]);
    atomicAdd(&g_Lu, softplusf(s));
}

__device__ __forceinline__ void sims_block(int blk, const float* __restrict__ embO,
                                           const float* __restrict__ embN,
                                           const int* __restrict__ edges, int nE) {
    int warp = (blk * 256 + threadIdx.x) >> 5;
    int lane = threadIdx.x & 31;
    if (warp >= nE) return;
    int u = edges[2 * warp], v = edges[2 * warp + 1];
    const float4* uo = (const float4*)(embO + (long long)u * DEMB);
    const float4* vo = (const float4*)(embO + (long long)v * DEMB);
    const float4* un = (const float4*)(embN + (long long)u * DEMB);
    const float4* vn = (const float4*)(embN + (long long)v * DEMB);
    float4 a = uo[lane], b = vo[lane];
    float4 c = un[lane], d4 = vn[lane];
    float so = a.x * b.x + a.y * b.y + a.z * b.z + a.w * b.w;
    float sn = c.x * d4.x + c.y * d4.y + c.z * d4.z + c.w * d4.w;
#pragma unroll
    for (int o = 16; o; o >>= 1) {
        so += __shfl_xor_sync(~0u, so, o);
        sn += __shfl_xor_sync(~0u, sn, o);
    }
    if (lane == 0) {
        g_sims_o[warp] = so;
        g_sims_n[warp] = sn;
        atomicMax(&g_mkey_o[u], fkey(so));
        atomicMax(&g_mkey_n[u], fkey(sn));
    }
}

// K2: blocks [0,8192) deg rows | [8192,8208) lu | [8208,9232) sims
__global__ __launch_bounds__(256)
void mega1_kernel(const float4* __restrict__ A4, const void* __restrict__ mask,
                  const float* __restrict__ pred,
                  const float* __restrict__ embO, const float* __restrict__ embN,
                  const int* __restrict__ uE, int nU,
                  const int* __restrict__ rE, int nR) {
    int b = blockIdx.x;
    if (b < NA)            deg_cvt_block(b, A4, mask);
    else if (b < NA + 16)  lu_block(b - NA, pred, uE, nU);
    else                   sims_block(b - NA - 16, embO, embN, rE, nR);
}

// ---------------- K3: segsum + H transpose to fp8 ---------------------------
__device__ __forceinline__ void segsum_block(int blk, const int* __restrict__ edges, int nE) {
    int e = blk * 256 + threadIdx.x;
    if (e >= nE) return;
    int u = edges[2 * e];
    float mo = fkey_inv(g_mkey_o[u]);
    float mn = fkey_inv(g_mkey_n[u]);
    atomicAdd(&g_ssum_o[u], expf(g_sims_o[e] - mo));
    atomicAdd(&g_ssum_n[u], expf(g_sims_n[e] - mn));
    atomicAdd(&g_cnt[u], 1.f);
}

// Ht8[d][j] = e4m3(HS_SCALE * dinv_j * H[j][d]); block handles 64 j
__device__ void htrans_block(int blk, const float* __restrict__ H) {
    __shared__ unsigned char T[DEMB][64];     // 8KB
    int j0 = blk * 64;
    int tid = threadIdx.x;
    {
        int jl = tid >> 2;                    // 0..63
        int dg = (tid & 3) * 32;              // 0,32,64,96
        int j = j0 + jl;
        float dv = g_dinv[j] * HS_SCALE;
        const float4* hb = (const float4*)(H + (long long)j * DEMB + dg);
#pragma unroll
        for (int q = 0; q < 8; q++) {
            float4 h = hb[q];
            uint32_t u = e4m3x4(h.x * dv, h.y * dv, h.z * dv, h.w * dv);
            int d = dg + q * 4;
            T[d + 0][jl] = (unsigned char)(u);
            T[d + 1][jl] = (unsigned char)(u >> 8);
            T[d + 2][jl] = (unsigned char)(u >> 16);
            T[d + 3][jl] = (unsigned char)(u >> 24);
        }
    }
    __syncthreads();
    {
        int d = tid >> 1;
        int half = tid & 1;
        uint2 v = *(const uint2*)&T[d][half * 32];
        uint2 w = *(const uint2*)&T[d][half * 32 + 8];
        uint2 x = *(const uint2*)&T[d][half * 32 + 16];
        uint2 y = *(const uint2*)&T[d][half * 32 + 24];
        uint4 o1 = make_uint4(v.x, v.y, w.x, w.y);
        uint4 o2 = make_uint4(x.x, x.y, y.x, y.y);
        *(uint4*)&g_Ht8[(long long)d * NA + j0 + half * 32]      = o1;
        *(uint4*)&g_Ht8[(long long)d * NA + j0 + half * 32 + 16] = o2;
    }
}

__global__ __launch_bounds__(256)
void mega2_kernel(const int* __restrict__ rE, int nR, const float* __restrict__ H) {
    int b = blockIdx.x;
    if (b < 32) segsum_block(b, rE, nR);
    else        htrans_block(b - 32, H);
}

// ---------------- K4: gemm (blocks 0..127) + lp (blocks 128..159) -----------
// Pure fp8 e4m3 MMA: A = W8 (row-major, k contig), B = Ht8 (d-major, k contig).
#define MBLK   64
#define KBLK   128
#define STAGES 4
#define NCHUNK (NA / KBLK)              // 64
#define OFF_A8  0                       // A fp8 tile 64x128  = 8192
#define OFF_B8  8192                    // B fp8 tile 128x128 = 16384
#define STAGEB  24576
#define GEMM_SMEM (STAGES * STAGEB)     // 98304

__device__ __forceinline__ void lp_block(int blk, const int* __restrict__ edges, int nE) {
    int e = blk * 256 + threadIdx.x;
    if (e >= nE) return;
    int u = edges[2 * e];
    if (g_cnt[u] <= 1.f) return;
    float mo = fkey_inv(g_mkey_o[u]);
    float lseo = logf(g_ssum_o[u] + 1e-30f) + mo;
    float lpo  = logf(expf(g_sims_o[e] - lseo) + FEPS);
    float mn = fkey_inv(g_mkey_n[u]);
    float lsen = logf(g_ssum_n[u] + 1e-30f) + mn;
    float lpn  = logf(expf(g_sims_n[e] - lsen) + FEPS);
    float d = lpn - lpo;
    atomicAdd(&g_LpNum, d * d);
    atomicAdd(&g_LpDen, 1.f);
}

__device__ void gemm_block(const float* __restrict__ H, char* smem) {
    __shared__ float s_num[MBLK], s_sq[MBLK];
    uint32_t sb = s2u(smem);
    const int tid = threadIdx.x;
    const int lane = tid & 31;
    const int wid = tid >> 5;
    const int wm = wid & 1;              // 0..1 (M)
    const int wn = wid >> 1;             // 0..3 (N)
    const int bi = blockIdx.x * MBLK;

    if (tid < MBLK) { s_num[tid] = 0.f; s_sq[tid] = 0.f; }

    const unsigned char* __restrict__ W  = g_W8;
    const unsigned char* __restrict__ Ht = g_Ht8;

    const int a_r0 = tid >> 3;           // A cp rows: a_r0, a_r0+32
    const int a_cc = tid & 7;

    auto issue_loads = [&](int n) {
        uint32_t st = sb + (n % STAGES) * STAGEB;
        long long j0 = (long long)n * KBLK;
        // A fp8: 64 rows x 128B = 512 cp16 (2/thread)
#pragma unroll
        for (int q = 0; q < 2; q++) {
            int r = a_r0 + q * 32;
            cp16(st + OFF_A8 + r * 128 + ((a_cc ^ (r & 7)) << 4),
                 W + (long long)(bi + r) * NA + j0 + a_cc * 16);
        }
        // B fp8: 128 d-rows x 128B = 1024 cp16 (4/thread)
#pragma unroll
        for (int q = 0; q < 4; q++) {
            int id = tid + q * 256;
            int d = id >> 3, ck = id & 7;
            cp16(st + OFF_B8 + d * 128 + ((ck ^ (d & 7)) << 4),
                 Ht + (long long)d * NA + j0 + ck * 16);
        }
        CP_COMMIT();
    };

    float acc[2][4][4];
#pragma unroll
    for (int mt = 0; mt < 2; mt++)
#pragma unroll
        for (int nt = 0; nt < 4; nt++)
#pragma unroll
            for (int q = 0; q < 4; q++) acc[mt][nt][q] = 0.f;

    const int grp = lane >> 3;                 // 0..3
    const int l7  = lane & 7;
    // A: m0=(rows,klo) m1=(rows+8,klo) m2=(rows,khi) m3=(rows+8,khi)
    const int ar_base = wm * 32 + l7 + ((grp & 1) << 3);
    const int ac_add  = grp >> 1;
    // B: m0=(n,klo) m1=(n,khi) m2=(n+8,klo) m3=(n+8,khi)
    const int bn_base = l7 + ((grp >> 1) << 3);
    const int bc_add  = grp & 1;

    issue_loads(0); issue_loads(1); issue_loads(2);

    for (int c = 0; c < NCHUNK; c++) {
        CP_WAIT2();
        __syncthreads();
        uint32_t Ab = sb + (c % STAGES) * STAGEB + OFF_A8;
        uint32_t Bb = sb + (c % STAGES) * STAGEB + OFF_B8;

#pragma unroll
        for (int kk = 0; kk < 4; kk++) {       // four k32 steps
            uint32_t af[2][4];
#pragma unroll
            for (int mt = 0; mt < 2; mt++) {
                int r = ar_base + mt * 16;
                int ch = kk * 2 + ac_add;
                ldsm4(af[mt], Ab + (uint32_t)(r * 128 + ((ch ^ (r & 7)) << 4)));
            }
            uint32_t bf[4][2];
#pragma unroll
            for (int p = 0; p < 2; p++) {      // covers nt=2p, 2p+1
                int nrow = wn * 32 + p * 16 + bn_base;
                int ck = kk * 2 + bc_add;
                uint32_t t4[4];
                ldsm4(t4, Bb + (uint32_t)(nrow * 128 + ((ck ^ (nrow & 7)) << 4)));
                bf[2 * p + 0][0] = t4[0]; bf[2 * p + 0][1] = t4[1];
                bf[2 * p + 1][0] = t4[2]; bf[2 * p + 1][1] = t4[3];
            }
#pragma unroll
            for (int mt = 0; mt < 2; mt++)
#pragma unroll
                for (int nt = 0; nt < 4; nt++)
                    mma16832f8(acc[mt][nt], af[mt], bf[nt]);
        }

        int n = c + 3;
        if (n < NCHUNK) issue_loads(n);
        else            CP_COMMIT();
    }

    // ---- epilogue: per-row num = <H, acc>, sq = |acc|^2  (acc = HS_SCALE * X)
    __syncthreads();
#pragma unroll
    for (int mt = 0; mt < 2; mt++) {
#pragma unroll
        for (int half = 0; half < 2; half++) {
            int rl = wm * 32 + mt * 16 + half * 8 + (lane >> 2);
            long long gi = bi + rl;
            float num = 0.f, sq = 0.f;
#pragma unroll
            for (int nt = 0; nt < 4; nt++) {
                int col = wn * 32 + nt * 8 + (lane & 3) * 2;
                float v0 = acc[mt][nt][half * 2 + 0];
                float v1 = acc[mt][nt][half * 2 + 1];
                float h0 = H[gi * DEMB + col];
                float h1 = H[gi * DEMB + col + 1];
                num += h0 * v0 + h1 * v1;
                sq  += v0 * v0 + v1 * v1;
            }
            num += __shfl_xor_sync(~0u, num, 1);
            num += __shfl_xor_sync(~0u, num, 2);
            sq  += __shfl_xor_sync(~0u, sq, 1);
            sq  += __shfl_xor_sync(~0u, sq, 2);
            if ((lane & 3) == 0) {
                atomicAdd(&s_num[rl], num);
                atomicAdd(&s_sq[rl], sq);
            }
        }
    }
    __syncthreads();

    if (tid < MBLK) {
        long long gi = bi + tid;
        const float4* hb = (const float4*)(H + gi * DEMB);
        float hsq = 0.f;
#pragma unroll
        for (int q = 0; q < 32; q++) {
            float4 h = hb[q];
            hsq += h.x * h.x + h.y * h.y + h.z * h.z + h.w * h.w;
        }
        float num = s_num[tid] * (1.0f / HS_SCALE);
        float sq  = s_sq[tid]  * (1.0f / (HS_SCALE * HS_SCALE));
        float dv  = g_dinv[gi];
        float den = fmaxf(sqrtf(hsq) * (dv * sqrtf(sq)), FEPS);
        float cosv = dv * num / den;
        float val = softplusf(-cosv);
#pragma unroll
        for (int o = 16; o; o >>= 1) val += __shfl_xor_sync(~0u, val, o);
        if ((tid & 31) == 0) atomicAdd(&g_Lc, val);
    }
}

__global__ __launch_bounds__(256, 1)
void mega3_kernel(const float* __restrict__ H, const int* __restrict__ rE, int nR) {
    extern __shared__ char smem[];
    if (blockIdx.x < 128) gemm_block(H, smem);
    else                  lp_block(blockIdx.x - 128, rE, nR);
}

// ---------------- finalize --------------------------------------------------
__global__ void final_kernel(float* __restrict__ out, int nU) {
    float L_u = g_Lu / (float)nU;
    float L_p = g_LpNum / fmaxf(g_LpDen, 1.f);
    float L_c = g_Lc / (float)NA;
    out[0] = L_u + L_p + 0.01f * L_c;
    out[1] = L_u;
    out[2] = L_p;
    out[3] = L_c;
}

// ---------------- launch ----------------------------------------------------
extern "C" void kernel_launch(void* const* d_in, const int* in_sizes, int n_in,
                              void* d_out, int out_size) {
    const float* pred = (const float*)d_in[0];
    const float* embO = (const float*)d_in[1];
    const float* embN = (const float*)d_in[2];
    const float* A    = (const float*)d_in[3];
    const float* H    = (const float*)d_in[4];
    const int*   uE   = (const int*)d_in[5];
    const int*   rE   = (const int*)d_in[6];
    const void*  mask = d_in[7];
    int nU = in_sizes[5] / 2;
    int nR = in_sizes[6] / 2;

    cudaFuncSetAttribute(mega3_kernel,
                         cudaFuncAttributeMaxDynamicSharedMemorySize, GEMM_SMEM);

    init_kernel<<<(NEMB + 255) / 256, 256>>>((const unsigned*)mask);
    mega1_kernel<<<NA + 16 + 1024, 256>>>((const float4*)A, mask, pred,
                                          embO, embN, uE, nU, rE, nR);
    mega2_kernel<<<32 + NA / 64, 256>>>(rE, nR, H);
    mega3_kernel<<<128 + 32, 256, GEMM_SMEM>>>(H, rE, nR);
    final_kernel<<<1, 1>>>((float*)d_out, nU);
}

// round 10
// speedup vs baseline: 1.2185x; 1.2185x over previous
#include <cuda_runtime.h>
#include <cuda_bf16.h>
#include <cuda_fp16.h>
#include <math.h>
#include <stdint.h>

#define NEMB 20000
#define DEMB 128
#define NA   8192
#define PDIM 10000
#define FEPS 1e-8f
#define HS_SCALE 64.0f

// ---------------- scratch (device globals; no allocation allowed) ----------
__device__ float    g_sims_o[NA];
__device__ float    g_sims_n[NA];
__device__ unsigned g_mkey_o[NEMB];
__device__ unsigned g_mkey_n[NEMB];
__device__ float    g_ssum_o[NEMB];
__device__ float    g_ssum_n[NEMB];
__device__ float    g_cnt[NEMB];
__device__ float    g_dinv[NA];
__device__ float    g_Lu, g_LpNum, g_LpDen, g_Lc;
__device__ int      g_mask_mode;   // 0 = byte(bool), 1 = int32, 2 = float32

// W = e4m3(A * mask) (64 MB), Hs = f16(HS_SCALE * dinv_j * H[j][:]) (2 MB)
__device__ unsigned char  g_W8[(size_t)NA * NA];
__device__ unsigned short g_Hs[(size_t)NA * DEMB];

// ---------------- helpers ---------------------------------------------------
__device__ __forceinline__ unsigned fkey(float f) {
    unsigned u = __float_as_uint(f);
    return (u & 0x80000000u) ? ~u : (u | 0x80000000u);
}
__device__ __forceinline__ float fkey_inv(unsigned k) {
    return (k & 0x80000000u) ? __uint_as_float(k & 0x7fffffffu)
                             : __uint_as_float(~k);
}
__device__ __forceinline__ float4 mask4(const void* m, int mode, int idx4) {
    float4 r;
    if (mode == 0) {                       // packed bytes (bool)
        unsigned w = __ldcs(&((const unsigned*)m)[idx4]);
        r.x = (w & 0x000000ffu) ? 1.f : 0.f;
        r.y = (w & 0x0000ff00u) ? 1.f : 0.f;
        r.z = (w & 0x00ff0000u) ? 1.f : 0.f;
        r.w = (w & 0xff000000u) ? 1.f : 0.f;
    } else if (mode == 1) {                // int32 0/1
        int4 v = __ldcs(&((const int4*)m)[idx4]);
        r.x = v.x ? 1.f : 0.f; r.y = v.y ? 1.f : 0.f;
        r.z = v.z ? 1.f : 0.f; r.w = v.w ? 1.f : 0.f;
    } else {                               // float32
        r = __ldcs(&((const float4*)m)[idx4]);
    }
    return r;
}
__device__ __forceinline__ float softplusf(float x) {
    return fmaxf(x, 0.f) + log1pf(expf(-fabsf(x)));
}
__device__ __forceinline__ uint32_t s2u(const void* p) {
    uint32_t a;
    asm("{ .reg .u64 t; cvta.to.shared.u64 t, %1; cvt.u32.u64 %0, t; }"
        : "=r"(a) : "l"(p));
    return a;
}
__device__ __forceinline__ void cp16(uint32_t dst, const void* src) {
    asm volatile("cp.async.cg.shared.global [%0], [%1], 16;\n"
                 :: "r"(dst), "l"(src) : "memory");
}
#define CP_COMMIT() asm volatile("cp.async.commit_group;" ::: "memory")
#define CP_WAIT2()  asm volatile("cp.async.wait_group 2;" ::: "memory")

__device__ __forceinline__ void ldsm4(uint32_t* r, uint32_t addr) {
    asm volatile("ldmatrix.sync.aligned.m8n8.x4.shared.b16 {%0,%1,%2,%3}, [%4];"
                 : "=r"(r[0]), "=r"(r[1]), "=r"(r[2]), "=r"(r[3]) : "r"(addr));
}
__device__ __forceinline__ void ldsm4t(uint32_t* r, uint32_t addr) {
    asm volatile("ldmatrix.sync.aligned.m8n8.x4.trans.shared.b16 {%0,%1,%2,%3}, [%4];"
                 : "=r"(r[0]), "=r"(r[1]), "=r"(r[2]), "=r"(r[3]) : "r"(addr));
}
__device__ __forceinline__ void mma16816(float* c, const uint32_t* a, const uint32_t* b) {
    asm volatile(
        "mma.sync.aligned.m16n8k16.row.col.f32.f16.f16.f32 "
        "{%0,%1,%2,%3}, {%4,%5,%6,%7}, {%8,%9}, {%0,%1,%2,%3};"
        : "+f"(c[0]), "+f"(c[1]), "+f"(c[2]), "+f"(c[3])
        : "r"(a[0]), "r"(a[1]), "r"(a[2]), "r"(a[3]), "r"(b[0]), "r"(b[1]));
}
// pack 4 floats -> 4 e4m3 bytes (x0 at lowest byte)
__device__ __forceinline__ uint32_t e4m3x4(float x0, float x1, float x2, float x3) {
    uint16_t lo, hi;
    asm("cvt.rn.satfinite.e4m3x2.f32 %0, %1, %2;" : "=h"(lo) : "f"(x1), "f"(x0));
    asm("cvt.rn.satfinite.e4m3x2.f32 %0, %1, %2;" : "=h"(hi) : "f"(x3), "f"(x2));
    return (uint32_t)lo | ((uint32_t)hi << 16);
}
// 4 packed e4m3 -> two f16x2 regs (elementwise, lo->lo)
__device__ __forceinline__ void f8x4_to_f16x4(uint32_t w, uint32_t& lo, uint32_t& hi) {
    uint16_t a, b;
    asm("mov.b32 {%0,%1}, %2;" : "=h"(a), "=h"(b) : "r"(w));
    asm("cvt.rn.f16x2.e4m3x2 %0, %1;" : "=r"(lo) : "h"(a));
    asm("cvt.rn.f16x2.e4m3x2 %0, %1;" : "=r"(hi) : "h"(b));
}

// ---------------- K1: init + mask dtype detection ---------------------------
__global__ void init_kernel(const unsigned* __restrict__ m) {
    int i = blockIdx.x * blockDim.x + threadIdx.x;
    if (i < NEMB) {
        g_mkey_o[i] = 0u; g_mkey_n[i] = 0u;
        g_ssum_o[i] = 0.f; g_ssum_n[i] = 0.f;
        g_cnt[i] = 0.f;
    }
    if (i == 0) { g_Lu = 0.f; g_LpNum = 0.f; g_LpDen = 0.f; g_Lc = 0.f; }
    if (blockIdx.x == 0 && threadIdx.x < 32) {
        int vi = 0, vf = 0, vb = 0;
        for (int k = threadIdx.x; k < 256; k += 32) {
            unsigned w = m[k];
            if (w == 1u) vi++;
            else if (w == 0x3f800000u) vf++;
            else if (w != 0u) vb++;
        }
#pragma unroll
        for (int o = 16; o; o >>= 1) {
            vi += __shfl_xor_sync(~0u, vi, o);
            vf += __shfl_xor_sync(~0u, vf, o);
            vb += __shfl_xor_sync(~0u, vb, o);
        }
        if (threadIdx.x == 0) {
            int mode;
            if (vb >= vi && vb >= vf) mode = 0;
            else if (vi >= vf)        mode = 1;
            else                      mode = 2;
            g_mask_mode = mode;
        }
    }
}

// ---------------- K2 pieces -------------------------------------------------
__device__ __forceinline__ void deg_cvt_block(int row, const float4* __restrict__ A4,
                                              const void* __restrict__ mask) {
    int mode = g_mask_mode;
    int base4 = row * (NA / 4);
    unsigned* __restrict__ W4 = (unsigned*)g_W8;    // 4 fp8 per unsigned
    float s = 0.f;
#pragma unroll 4
    for (int c = threadIdx.x; c < NA / 4; c += 256) {
        float4 a = __ldcs(&A4[base4 + c]);
        float4 m = mask4(mask, mode, base4 + c);
        float x0 = a.x * m.x, x1 = a.y * m.y, x2 = a.z * m.z, x3 = a.w * m.w;
        s += (x0 + x1) + (x2 + x3);
        W4[base4 + c] = e4m3x4(x0, x1, x2, x3);
    }
    __shared__ float red[8];
#pragma unroll
    for (int o = 16; o; o >>= 1) s += __shfl_xor_sync(~0u, s, o);
    if ((threadIdx.x & 31) == 0) red[threadIdx.x >> 5] = s;
    __syncthreads();
    if (threadIdx.x < 8) {
        float v = red[threadIdx.x];
#pragma unroll
        for (int o = 4; o; o >>= 1) v += __shfl_xor_sync(0xffu, v, o);
        if (threadIdx.x == 0) g_dinv[row] = rsqrtf(v + FEPS);
    }
}

__device__ __forceinline__ void lu_block(int blk, const float* __restrict__ pred,
                                         const int* __restrict__ edges, int nE) {
    int e = blk * 256 + threadIdx.x;
    if (e >= nE) return;
    int u = edges[2 * e], v = edges[2 * e + 1];
    float s = __ldg(&pred[(long long)u * PDIM + v]);
    atomicAdd(&g_Lu, softplusf(s));
}

__device__ __forceinline__ void sims_block(int blk, const float* __restrict__ embO,
                                           const float* __restrict__ embN,
                                           const int* __restrict__ edges, int nE) {
    int warp = (blk * 256 + threadIdx.x) >> 5;
    int lane = threadIdx.x & 31;
    if (warp >= nE) return;
    int u = edges[2 * warp], v = edges[2 * warp + 1];
    const float4* uo = (const float4*)(embO + (long long)u * DEMB);
    const float4* vo = (const float4*)(embO + (long long)v * DEMB);
    const float4* un = (const float4*)(embN + (long long)u * DEMB);
    const float4* vn = (const float4*)(embN + (long long)v * DEMB);
    float4 a = uo[lane], b = vo[lane];
    float4 c = un[lane], d4 = vn[lane];
    float so = a.x * b.x + a.y * b.y + a.z * b.z + a.w * b.w;
    float sn = c.x * d4.x + c.y * d4.y + c.z * d4.z + c.w * d4.w;
#pragma unroll
    for (int o = 16; o; o >>= 1) {
        so += __shfl_xor_sync(~0u, so, o);
        sn += __shfl_xor_sync(~0u, sn, o);
    }
    if (lane == 0) {
        g_sims_o[warp] = so;
        g_sims_n[warp] = sn;
        atomicMax(&g_mkey_o[u], fkey(so));
        atomicMax(&g_mkey_n[u], fkey(sn));
    }
}

// K2: blocks [0,8192) deg rows | [8192,8208) lu | [8208,9232) sims
__global__ __launch_bounds__(256)
void mega1_kernel(const float4* __restrict__ A4, const void* __restrict__ mask,
                  const float* __restrict__ pred,
                  const float* __restrict__ embO, const float* __restrict__ embN,
                  const int* __restrict__ uE, int nU,
                  const int* __restrict__ rE, int nR) {
    int b = blockIdx.x;
    if (b < NA)            deg_cvt_block(b, A4, mask);
    else if (b < NA + 16)  lu_block(b - NA, pred, uE, nU);
    else                   sims_block(b - NA - 16, embO, embN, rE, nR);
}

// ---------------- K3: segsum + hscale ---------------------------------------
__device__ __forceinline__ void segsum_block(int blk, const int* __restrict__ edges, int nE) {
    int e = blk * 256 + threadIdx.x;
    if (e >= nE) return;
    int u = edges[2 * e];
    float mo = fkey_inv(g_mkey_o[u]);
    float mn = fkey_inv(g_mkey_n[u]);
    atomicAdd(&g_ssum_o[u], expf(g_sims_o[e] - mo));
    atomicAdd(&g_ssum_n[u], expf(g_sims_n[e] - mn));
    atomicAdd(&g_cnt[u], 1.f);
}

__device__ __forceinline__ void hscale_block(int blk, const float4* __restrict__ H4) {
    int i = blk * 256 + threadIdx.x;
    if (i >= NA * DEMB / 4) return;
    int j = i >> 5;
    float dv = g_dinv[j] * HS_SCALE;
    float4 h = H4[i];
    __half2 p0 = __floats2half2_rn(h.x * dv, h.y * dv);
    __half2 p1 = __floats2half2_rn(h.z * dv, h.w * dv);
    uint2 o;
    o.x = *(unsigned*)&p0;
    o.y = *(unsigned*)&p1;
    ((uint2*)g_Hs)[i] = o;
}

__global__ __launch_bounds__(256)
void mega2_kernel(const int* __restrict__ rE, int nR, const float4* __restrict__ H4) {
    int b = blockIdx.x;
    if (b < 32) segsum_block(b, rE, nR);
    else        hscale_block(b - 32, H4);
}

// ---------------- K4: gemm (blocks 0..127) + lp (blocks 128..143) -----------
// 512 threads, 16 warps: warps 0-7 do k16 steps 0-3, warps 8-15 do steps 4-7
// of each KBLK=128 chunk; partial accumulators merged via smem pre-epilogue.
#define MBLK   64
#define KBLK   128
#define STAGES 4
#define NCHUNK (NA / KBLK)              // 64
#define OFF_A8  0                       // A fp8 tile 64x128  = 8192
#define OFF_B   8192                    // B f16 tile 128x128 = 32768
#define STAGEB  40960
#define OFF_A16 (STAGES * STAGEB)       // A f16 tile 64x128 x2 bufs = 32768
#define GEMM_SMEM (OFF_A16 + 2 * 16384) // 196608

__device__ __forceinline__ void lp_block(int blk, const int* __restrict__ edges, int nE) {
    int e = blk * 512 + threadIdx.x;
    if (e >= nE) return;
    int u = edges[2 * e];
    if (g_cnt[u] <= 1.f) return;
    float mo = fkey_inv(g_mkey_o[u]);
    float lseo = logf(g_ssum_o[u] + 1e-30f) + mo;
    float lpo  = logf(expf(g_sims_o[e] - lseo) + FEPS);
    float mn = fkey_inv(g_mkey_n[u]);
    float lsen = logf(g_ssum_n[u] + 1e-30f) + mn;
    float lpn  = logf(expf(g_sims_n[e] - lsen) + FEPS);
    float d = lpn - lpo;
    atomicAdd(&g_LpNum, d * d);
    atomicAdd(&g_LpDen, 1.f);
}

__device__ void gemm_block(const float* __restrict__ H, char* smem) {
    __shared__ float s_num[MBLK], s_sq[MBLK];
    uint32_t sb = s2u(smem);
    const int tid = threadIdx.x;
    const int lane = tid & 31;
    const int wid = tid >> 5;            // 0..15
    const int wk = wid >> 3;             // k-half 0..1
    const int w8 = wid & 7;
    const int wm = w8 & 1;               // 0..1 (M)
    const int wn = w8 >> 1;              // 0..3 (N)
    const int bi = blockIdx.x * MBLK;

    if (tid < MBLK) { s_num[tid] = 0.f; s_sq[tid] = 0.f; }

    const unsigned char*  __restrict__ W  = g_W8;
    const unsigned short* __restrict__ Hs = g_Hs;

    // A fp8 cp mapping: 512 cp16 -> 1/thread. r = tid>>3, chunk = tid&7
    const int a_r = tid >> 3;
    const int a_cc = tid & 7;

    auto issue_loads = [&](int n) {
        uint32_t st = sb + (n % STAGES) * STAGEB;
        long long j0 = (long long)n * KBLK;
        cp16(st + OFF_A8 + a_r * 128 + ((a_cc ^ (a_r & 7)) << 4),
             W + (long long)(bi + a_r) * NA + j0 + a_cc * 16);
#pragma unroll
        for (int q = 0; q < 4; q++) {       // B: 2048 cp16 -> 4/thread
            int id = tid + q * 512;
            int k = id >> 4, c = id & 15;
            cp16(st + OFF_B + k * 256 + ((c ^ (k & 7)) << 4),
                 Hs + (j0 + k) * DEMB + c * 8);
        }
        CP_COMMIT();
    };

    // convert OWN cp'd fp8 bytes (row a_r, chunk a_cc) -> f16 buf
    auto cvt_tile = [&](int n) {
        char* src = smem + (n % STAGES) * STAGEB + OFF_A8;
        char* dst = smem + OFF_A16 + (n & 1) * 16384;
        uint4 w = *(const uint4*)(src + a_r * 128 + ((a_cc ^ (a_r & 7)) << 4));
        uint4 o1, o2;
        f8x4_to_f16x4(w.x, o1.x, o1.y);
        f8x4_to_f16x4(w.y, o1.z, o1.w);
        f8x4_to_f16x4(w.z, o2.x, o2.y);
        f8x4_to_f16x4(w.w, o2.z, o2.w);
        int ch0 = a_cc * 2, ch1 = a_cc * 2 + 1;
        *(uint4*)(dst + a_r * 256 + ((ch0 ^ (a_r & 7)) << 4)) = o1;
        *(uint4*)(dst + a_r * 256 + ((ch1 ^ (a_r & 7)) << 4)) = o2;
    };

    float acc[2][4][4];
#pragma unroll
    for (int mt = 0; mt < 2; mt++)
#pragma unroll
        for (int nt = 0; nt < 4; nt++)
#pragma unroll
            for (int q = 0; q < 4; q++) acc[mt][nt][q] = 0.f;

    const int grp = lane >> 3;                 // 0..3
    const int l7  = lane & 7;
    const int ar_base = wm * 32 + l7 + ((grp & 1) << 3);
    const int ac_add  = grp >> 1;
    const int bk_base = l7 + ((grp & 1) << 3);
    const int bc_add  = grp >> 1;

    issue_loads(0); issue_loads(1); issue_loads(2);
    CP_WAIT2();                 // own group-0 copies complete
    cvt_tile(0);
    __syncthreads();

    for (int c = 0; c < NCHUNK; c++) {
        int n = c + 3;
        if (n < NCHUNK) issue_loads(n);
        else            CP_COMMIT();

        uint32_t Ab = sb + OFF_A16 + (c & 1) * 16384;
        uint32_t Bb = sb + (c % STAGES) * STAGEB + OFF_B;

#pragma unroll
        for (int kk2 = 0; kk2 < 4; kk2++) {    // this warp's k16 steps
            int kk = wk * 4 + kk2;
            uint32_t af[2][4];
#pragma unroll
            for (int mt = 0; mt < 2; mt++) {
                int r = ar_base + mt * 16;
                int ch = kk * 2 + ac_add;
                ldsm4(af[mt], Ab + (uint32_t)(r * 256 + ((ch ^ (r & 7)) << 4)));
            }
            uint32_t bf[4][2];
#pragma unroll
            for (int cp = 0; cp < 2; cp++) {
                int k = kk * 16 + bk_base;
                int cn = wn * 4 + cp * 2 + bc_add;
                uint32_t t4[4];
                ldsm4t(t4, Bb + (uint32_t)(k * 256 + ((cn ^ (k & 7)) << 4)));
                bf[cp * 2 + 0][0] = t4[0]; bf[cp * 2 + 0][1] = t4[1];
                bf[cp * 2 + 1][0] = t4[2]; bf[cp * 2 + 1][1] = t4[3];
            }
#pragma unroll
            for (int mt = 0; mt < 2; mt++)
#pragma unroll
                for (int nt = 0; nt < 4; nt++)
                    mma16816(acc[mt][nt], af[mt], bf[nt]);
        }

        if (c + 1 < NCHUNK) {
            CP_WAIT2();          // own group c+1 copies complete
            cvt_tile(c + 1);
        }
        __syncthreads();
    }

    // ---- merge k-half partial accumulators (|Hp|^2 is nonlinear) ----
    // layout: [w8 pair][reg idx][lane] -> lane-contiguous, conflict-free
    float* mbuf = (float*)smem;
    if (wk == 1) {
        float* dst = mbuf + w8 * 1024 + lane;
        int idx = 0;
#pragma unroll
        for (int mt = 0; mt < 2; mt++)
#pragma unroll
            for (int nt = 0; nt < 4; nt++)
#pragma unroll
                for (int q = 0; q < 4; q++) dst[(idx++) * 32] = acc[mt][nt][q];
    }
    __syncthreads();
    if (wk == 0) {
        const float* src = mbuf + w8 * 1024 + lane;
        int idx = 0;
#pragma unroll
        for (int mt = 0; mt < 2; mt++)
#pragma unroll
            for (int nt = 0; nt < 4; nt++)
#pragma unroll
                for (int q = 0; q < 4; q++) acc[mt][nt][q] += src[(idx++) * 32];

        // ---- epilogue: per-row num = <H, acc>, sq = |acc|^2 ----
#pragma unroll
        for (int mt = 0; mt < 2; mt++) {
#pragma unroll
            for (int half = 0; half < 2; half++) {
                int rl = wm * 32 + mt * 16 + half * 8 + (lane >> 2);
                long long gi = bi + rl;
                float num = 0.f, sq = 0.f;
#pragma unroll
                for (int nt = 0; nt < 4; nt++) {
                    int col = wn * 32 + nt * 8 + (lane & 3) * 2;
                    float v0 = acc[mt][nt][half * 2 + 0];
                    float v1 = acc[mt][nt][half * 2 + 1];
                    float h0 = H[gi * DEMB + col];
                    float h1 = H[gi * DEMB + col + 1];
                    num += h0 * v0 + h1 * v1;
                    sq  += v0 * v0 + v1 * v1;
                }
                num += __shfl_xor_sync(~0u, num, 1);
                num += __shfl_xor_sync(~0u, num, 2);
                sq  += __shfl_xor_sync(~0u, sq, 1);
                sq  += __shfl_xor_sync(~0u, sq, 2);
                if ((lane & 3) == 0) {
                    atomicAdd(&s_num[rl], num);
                    atomicAdd(&s_sq[rl], sq);
                }
            }
        }
    }
    __syncthreads();

    if (tid < MBLK) {
        long long gi = bi + tid;
        const float4* hb = (const float4*)(H + gi * DEMB);
        float hsq = 0.f;
#pragma unroll
        for (int q = 0; q < 32; q++) {
            float4 h = hb[q];
            hsq += h.x * h.x + h.y * h.y + h.z * h.z + h.w * h.w;
        }
        float num = s_num[tid] * (1.0f / HS_SCALE);
        float sq  = s_sq[tid]  * (1.0f / (HS_SCALE * HS_SCALE));
        float dv  = g_dinv[gi];
        float den = fmaxf(sqrtf(hsq) * (dv * sqrtf(sq)), FEPS);
        float cosv = dv * num / den;
        float val = softplusf(-cosv);
#pragma unroll
        for (int o = 16; o; o >>= 1) val += __shfl_xor_sync(~0u, val, o);
        if ((tid & 31) == 0) atomicAdd(&g_Lc, val);
    }
}

__global__ __launch_bounds__(512, 1)
void mega3_kernel(const float* __restrict__ H, const int* __restrict__ rE, int nR) {
    extern __shared__ char smem[];
    if (blockIdx.x < 128) gemm_block(H, smem);
    else                  lp_block(blockIdx.x - 128, rE, nR);
}

// ---------------- finalize --------------------------------------------------
__global__ void final_kernel(float* __restrict__ out, int nU) {
    float L_u = g_Lu / (float)nU;
    float L_p = g_LpNum / fmaxf(g_LpDen, 1.f);
    float L_c = g_Lc / (float)NA;
    out[0] = L_u + L_p + 0.01f * L_c;
    out[1] = L_u;
    out[2] = L_p;
    out[3] = L_c;
}

// ---------------- launch ----------------------------------------------------
extern "C" void kernel_launch(void* const* d_in, const int* in_sizes, int n_in,
                              void* d_out, int out_size) {
    const float* pred = (const float*)d_in[0];
    const float* embO = (const float*)d_in[1];
    const float* embN = (const float*)d_in[2];
    const float* A    = (const float*)d_in[3];
    const float* H    = (const float*)d_in[4];
    const int*   uE   = (const int*)d_in[5];
    const int*   rE   = (const int*)d_in[6];
    const void*  mask = d_in[7];
    int nU = in_sizes[5] / 2;
    int nR = in_sizes[6] / 2;

    cudaFuncSetAttribute(mega3_kernel,
                         cudaFuncAttributeMaxDynamicSharedMemorySize, GEMM_SMEM);

    init_kernel<<<(NEMB + 255) / 256, 256>>>((const unsigned*)mask);
    mega1_kernel<<<NA + 16 + 1024, 256>>>((const float4*)A, mask, pred,
                                          embO, embN, uE, nU, rE, nR);
    mega2_kernel<<<32 + 1024, 256>>>(rE, nR, (const float4*)H);
    mega3_kernel<<<128 + 16, 512, GEMM_SMEM>>>(H, rE, nR);
    final_kernel<<<1, 1>>>((float*)d_out, nU);
}

// round 11
// speedup vs baseline: 1.2726x; 1.0444x over previous
#include <cuda_runtime.h>
#include <cuda_bf16.h>
#include <cuda_fp16.h>
#include <math.h>
#include <stdint.h>

#define NEMB 20000
#define DEMB 128
#define NA   8192
#define PDIM 10000
#define FEPS 1e-8f
#define HS_SCALE 64.0f

// ---------------- scratch (device globals; no allocation allowed) ----------
__device__ float    g_sims_o[NA];
__device__ float    g_sims_n[NA];
__device__ unsigned g_mkey_o[NEMB];
__device__ unsigned g_mkey_n[NEMB];
__device__ float    g_ssum_o[NEMB];
__device__ float    g_ssum_n[NEMB];
__device__ float    g_cnt[NEMB];
__device__ float    g_dinv[NA];
__device__ float    g_Lu, g_LpNum, g_LpDen, g_Lc;
__device__ int      g_mask_mode;   // 0 = byte(bool), 1 = int32, 2 = float32

// W = e4m3(A * mask) (64 MB)
// Hs = f16(HS_SCALE * dinv_j * H[j][:]) with rows k-permuted within 16-blocks (2 MB)
__device__ unsigned char  g_W8[(size_t)NA * NA];
__device__ unsigned short g_Hs[(size_t)NA * DEMB];

// ---------------- helpers ---------------------------------------------------
__device__ __forceinline__ unsigned fkey(float f) {
    unsigned u = __float_as_uint(f);
    return (u & 0x80000000u) ? ~u : (u | 0x80000000u);
}
__device__ __forceinline__ float fkey_inv(unsigned k) {
    return (k & 0x80000000u) ? __uint_as_float(k & 0x7fffffffu)
                             : __uint_as_float(~k);
}
__device__ __forceinline__ float4 mask4(const void* m, int mode, int idx4) {
    float4 r;
    if (mode == 0) {                       // packed bytes (bool)
        unsigned w = __ldcs(&((const unsigned*)m)[idx4]);
        r.x = (w & 0x000000ffu) ? 1.f : 0.f;
        r.y = (w & 0x0000ff00u) ? 1.f : 0.f;
        r.z = (w & 0x00ff0000u) ? 1.f : 0.f;
        r.w = (w & 0xff000000u) ? 1.f : 0.f;
    } else if (mode == 1) {                // int32 0/1
        int4 v = __ldcs(&((const int4*)m)[idx4]);
        r.x = v.x ? 1.f : 0.f; r.y = v.y ? 1.f : 0.f;
        r.z = v.z ? 1.f : 0.f; r.w = v.w ? 1.f : 0.f;
    } else {                               // float32
        r = __ldcs(&((const float4*)m)[idx4]);
    }
    return r;
}
__device__ __forceinline__ float softplusf(float x) {
    return fmaxf(x, 0.f) + log1pf(expf(-fabsf(x)));
}
__device__ __forceinline__ uint32_t s2u(const void* p) {
    uint32_t a;
    asm("{ .reg .u64 t; cvta.to.shared.u64 t, %1; cvt.u32.u64 %0, t; }"
        : "=r"(a) : "l"(p));
    return a;
}
__device__ __forceinline__ void cp16(uint32_t dst, const void* src) {
    asm volatile("cp.async.cg.shared.global [%0], [%1], 16;\n"
                 :: "r"(dst), "l"(src) : "memory");
}
#define CP_COMMIT() asm volatile("cp.async.commit_group;" ::: "memory")
#define CP_WAIT2()  asm volatile("cp.async.wait_group 2;" ::: "memory")

__device__ __forceinline__ void ldsm4(uint32_t* r, uint32_t addr) {
    asm volatile("ldmatrix.sync.aligned.m8n8.x4.shared.b16 {%0,%1,%2,%3}, [%4];"
                 : "=r"(r[0]), "=r"(r[1]), "=r"(r[2]), "=r"(r[3]) : "r"(addr));
}
__device__ __forceinline__ void ldsm4t(uint32_t* r, uint32_t addr) {
    asm volatile("ldmatrix.sync.aligned.m8n8.x4.trans.shared.b16 {%0,%1,%2,%3}, [%4];"
                 : "=r"(r[0]), "=r"(r[1]), "=r"(r[2]), "=r"(r[3]) : "r"(addr));
}
__device__ __forceinline__ void mma16816(float* c, const uint32_t* a, const uint32_t* b) {
    asm volatile(
        "mma.sync.aligned.m16n8k16.row.col.f32.f16.f16.f32 "
        "{%0,%1,%2,%3}, {%4,%5,%6,%7}, {%8,%9}, {%0,%1,%2,%3};"
        : "+f"(c[0]), "+f"(c[1]), "+f"(c[2]), "+f"(c[3])
        : "r"(a[0]), "r"(a[1]), "r"(a[2]), "r"(a[3]), "r"(b[0]), "r"(b[1]));
}
// pack 4 floats -> 4 e4m3 bytes (x0 at lowest byte)
__device__ __forceinline__ uint32_t e4m3x4(float x0, float x1, float x2, float x3) {
    uint16_t lo, hi;
    asm("cvt.rn.satfinite.e4m3x2.f32 %0, %1, %2;" : "=h"(lo) : "f"(x1), "f"(x0));
    asm("cvt.rn.satfinite.e4m3x2.f32 %0, %1, %2;" : "=h"(hi) : "f"(x3), "f"(x2));
    return (uint32_t)lo | ((uint32_t)hi << 16);
}
// 4 packed e4m3 -> two f16x2 regs (elementwise, lo->lo)
__device__ __forceinline__ void f8x4_to_f16x4(uint32_t w, uint32_t& lo, uint32_t& hi) {
    uint16_t a, b;
    asm("mov.b32 {%0,%1}, %2;" : "=h"(a), "=h"(b) : "r"(w));
    asm("cvt.rn.f16x2.e4m3x2 %0, %1;" : "=r"(lo) : "h"(a));
    asm("cvt.rn.f16x2.e4m3x2 %0, %1;" : "=r"(hi) : "h"(b));
}

// ---------------- K1: init + mask dtype detection ---------------------------
__global__ void init_kernel(const unsigned* __restrict__ m) {
    int i = blockIdx.x * blockDim.x + threadIdx.x;
    if (i < NEMB) {
        g_mkey_o[i] = 0u; g_mkey_n[i] = 0u;
        g_ssum_o[i] = 0.f; g_ssum_n[i] = 0.f;
        g_cnt[i] = 0.f;
    }
    if (i == 0) { g_Lu = 0.f; g_LpNum = 0.f; g_LpDen = 0.f; g_Lc = 0.f; }
    if (blockIdx.x == 0 && threadIdx.x < 32) {
        int vi = 0, vf = 0, vb = 0;
        for (int k = threadIdx.x; k < 256; k += 32) {
            unsigned w = m[k];
            if (w == 1u) vi++;
            else if (w == 0x3f800000u) vf++;
            else if (w != 0u) vb++;
        }
#pragma unroll
        for (int o = 16; o; o >>= 1) {
            vi += __shfl_xor_sync(~0u, vi, o);
            vf += __shfl_xor_sync(~0u, vf, o);
            vb += __shfl_xor_sync(~0u, vb, o);
        }
        if (threadIdx.x == 0) {
            int mode;
            if (vb >= vi && vb >= vf) mode = 0;
            else if (vi >= vf)        mode = 1;
            else                      mode = 2;
            g_mask_mode = mode;
        }
    }
}

// ---------------- K2 pieces -------------------------------------------------
__device__ __forceinline__ void deg_cvt_block(int row, const float4* __restrict__ A4,
                                              const void* __restrict__ mask) {
    int mode = g_mask_mode;
    int base4 = row * (NA / 4);
    unsigned* __restrict__ W4 = (unsigned*)g_W8;    // 4 fp8 per unsigned
    float s = 0.f;
#pragma unroll 4
    for (int c = threadIdx.x; c < NA / 4; c += 256) {
        float4 a = __ldcs(&A4[base4 + c]);
        float4 m = mask4(mask, mode, base4 + c);
        float x0 = a.x * m.x, x1 = a.y * m.y, x2 = a.z * m.z, x3 = a.w * m.w;
        s += (x0 + x1) + (x2 + x3);
        W4[base4 + c] = e4m3x4(x0, x1, x2, x3);
    }
    __shared__ float red[8];
#pragma unroll
    for (int o = 16; o; o >>= 1) s += __shfl_xor_sync(~0u, s, o);
    if ((threadIdx.x & 31) == 0) red[threadIdx.x >> 5] = s;
    __syncthreads();
    if (threadIdx.x < 8) {
        float v = red[threadIdx.x];
#pragma unroll
        for (int o = 4; o; o >>= 1) v += __shfl_xor_sync(0xffu, v, o);
        if (threadIdx.x == 0) g_dinv[row] = rsqrtf(v + FEPS);
    }
}

__device__ __forceinline__ void lu_block(int blk, const float* __restrict__ pred,
                                         const int* __restrict__ edges, int nE) {
    int e = blk * 256 + threadIdx.x;
    if (e >= nE) return;
    int u = edges[2 * e], v = edges[2 * e + 1];
    float s = __ldg(&pred[(long long)u * PDIM + v]);
    atomicAdd(&g_Lu, softplusf(s));
}

__device__ __forceinline__ void sims_block(int blk, const float* __restrict__ embO,
                                           const float* __restrict__ embN,
                                           const int* __restrict__ edges, int nE) {
    int warp = (blk * 256 + threadIdx.x) >> 5;
    int lane = threadIdx.x & 31;
    if (warp >= nE) return;
    int u = edges[2 * warp], v = edges[2 * warp + 1];
    const float4* uo = (const float4*)(embO + (long long)u * DEMB);
    const float4* vo = (const float4*)(embO + (long long)v * DEMB);
    const float4* un = (const float4*)(embN + (long long)u * DEMB);
    const float4* vn = (const float4*)(embN + (long long)v * DEMB);
    float4 a = uo[lane], b = vo[lane];
    float4 c = un[lane], d4 = vn[lane];
    float so = a.x * b.x + a.y * b.y + a.z * b.z + a.w * b.w;
    float sn = c.x * d4.x + c.y * d4.y + c.z * d4.z + c.w * d4.w;
#pragma unroll
    for (int o = 16; o; o >>= 1) {
        so += __shfl_xor_sync(~0u, so, o);
        sn += __shfl_xor_sync(~0u, sn, o);
    }
    if (lane == 0) {
        g_sims_o[warp] = so;
        g_sims_n[warp] = sn;
        atomicMax(&g_mkey_o[u], fkey(so));
        atomicMax(&g_mkey_n[u], fkey(sn));
    }
}

// K2: blocks [0,8192) deg rows | [8192,8208) lu | [8208,9232) sims
__global__ __launch_bounds__(256)
void mega1_kernel(const float4* __restrict__ A4, const void* __restrict__ mask,
                  const float* __restrict__ pred,
                  const float* __restrict__ embO, const float* __restrict__ embN,
                  const int* __restrict__ uE, int nU,
                  const int* __restrict__ rE, int nR) {
    int b = blockIdx.x;
    if (b < NA)            deg_cvt_block(b, A4, mask);
    else if (b < NA + 16)  lu_block(b - NA, pred, uE, nU);
    else                   sims_block(b - NA - 16, embO, embN, rE, nR);
}

// ---------------- K3: segsum + hscale (k-permuted rows) ---------------------
__device__ __forceinline__ void segsum_block(int blk, const int* __restrict__ edges, int nE) {
    int e = blk * 256 + threadIdx.x;
    if (e >= nE) return;
    int u = edges[2 * e];
    float mo = fkey_inv(g_mkey_o[u]);
    float mn = fkey_inv(g_mkey_n[u]);
    atomicAdd(&g_ssum_o[u], expf(g_sims_o[e] - mo));
    atomicAdd(&g_ssum_n[u], expf(g_sims_n[e] - mn));
    atomicAdd(&g_cnt[u], 1.f);
}

// Hs stored row for actual k j: permute within each 16-row block so that the
// fp8-A ldmatrix slot order matches: o=4c+d -> slot 2c + (d&1) + 8*(d>>1).
__device__ __forceinline__ void hscale_block(int blk, const float4* __restrict__ H4) {
    int i = blk * 256 + threadIdx.x;
    if (i >= NA * DEMB / 4) return;
    int j = i >> 5;                      // actual k row
    float dv = g_dinv[j] * HS_SCALE;
    float4 h = H4[i];
    __half2 p0 = __floats2half2_rn(h.x * dv, h.y * dv);
    __half2 p1 = __floats2half2_rn(h.z * dv, h.w * dv);
    uint2 o;
    o.x = *(unsigned*)&p0;
    o.y = *(unsigned*)&p1;
    int rem = j & 15;
    int c = rem >> 2, d = rem & 3;
    int js = (j & ~15) | (2 * c + (d & 1) + ((d >> 1) << 3));
    ((uint2*)g_Hs)[js * 32 + (i & 31)] = o;
}

__global__ __launch_bounds__(256)
void mega2_kernel(const int* __restrict__ rE, int nR, const float4* __restrict__ H4) {
    int b = blockIdx.x;
    if (b < 32) segsum_block(b, rE, nR);
    else        hscale_block(b - 32, H4);
}

// ---------------- K4: gemm (blocks 0..127) + lp (blocks 128..143) -----------
// A consumed as fp8 directly from smem (ldmatrix.b16 + in-register cvt);
// B = permuted f16 Hs. 16 warps = 2 k-halves x (2M x 4N).
#define MBLK   64
#define KBLK   128
#define STAGES 4
#define NCHUNK (NA / KBLK)              // 64
#define OFF_A8  0                       // A fp8 tile 64x128  = 8192
#define OFF_B   8192                    // B f16 tile 128x128 = 32768
#define STAGEB  40960
#define GEMM_SMEM (STAGES * STAGEB)     // 163840

__device__ __forceinline__ void lp_block(int blk, const int* __restrict__ edges, int nE) {
    int e = blk * 512 + threadIdx.x;
    if (e >= nE) return;
    int u = edges[2 * e];
    if (g_cnt[u] <= 1.f) return;
    float mo = fkey_inv(g_mkey_o[u]);
    float lseo = logf(g_ssum_o[u] + 1e-30f) + mo;
    float lpo  = logf(expf(g_sims_o[e] - lseo) + FEPS);
    float mn = fkey_inv(g_mkey_n[u]);
    float lsen = logf(g_ssum_n[u] + 1e-30f) + mn;
    float lpn  = logf(expf(g_sims_n[e] - lsen) + FEPS);
    float d = lpn - lpo;
    atomicAdd(&g_LpNum, d * d);
    atomicAdd(&g_LpDen, 1.f);
}

__device__ void gemm_block(const float* __restrict__ H, char* smem) {
    __shared__ float s_num[MBLK], s_sq[MBLK];
    uint32_t sb = s2u(smem);
    const int tid = threadIdx.x;
    const int lane = tid & 31;
    const int wid = tid >> 5;            // 0..15
    const int wk = wid >> 3;             // k-half 0..1
    const int w8 = wid & 7;
    const int wm = w8 & 1;               // 0..1 (M)
    const int wn = w8 >> 1;              // 0..3 (N)
    const int bi = blockIdx.x * MBLK;

    if (tid < MBLK) { s_num[tid] = 0.f; s_sq[tid] = 0.f; }

    const unsigned char*  __restrict__ W  = g_W8;
    const unsigned short* __restrict__ Hs = g_Hs;

    // A fp8 cp mapping: 512 cp16 -> 1/thread
    const int a_r = tid >> 3;
    const int a_cc = tid & 7;

    auto issue_loads = [&](int n) {
        uint32_t st = sb + (n % STAGES) * STAGEB;
        long long j0 = (long long)n * KBLK;
        cp16(st + OFF_A8 + a_r * 128 + ((a_cc ^ (a_r & 7)) << 4),
             W + (long long)(bi + a_r) * NA + j0 + a_cc * 16);
#pragma unroll
        for (int q = 0; q < 4; q++) {       // B: 2048 cp16 -> 4/thread
            int id = tid + q * 512;
            int k = id >> 4, c = id & 15;
            cp16(st + OFF_B + k * 256 + ((c ^ (k & 7)) << 4),
                 Hs + (j0 + k) * DEMB + c * 8);
        }
        CP_COMMIT();
    };

    float acc[2][4][4];
#pragma unroll
    for (int mt = 0; mt < 2; mt++)
#pragma unroll
        for (int nt = 0; nt < 4; nt++)
#pragma unroll
            for (int q = 0; q < 4; q++) acc[mt][nt][q] = 0.f;

    const int grp = lane >> 3;                 // 0..3
    const int l7  = lane & 7;
    // A fp8 ldsm: tile grp at (rowbase + 8*(grp&1), chunk + (grp>>1))
    const int a_row_off = ((grp & 1) << 3) + l7;
    const int a_ch_off  = grp >> 1;
    // B (unchanged identity mapping; storage is pre-permuted)
    const int bk_base = l7 + ((grp & 1) << 3);
    const int bc_add  = grp >> 1;

    issue_loads(0); issue_loads(1); issue_loads(2);
    CP_WAIT2();
    __syncthreads();

    for (int c = 0; c < NCHUNK; c++) {
        int n = c + 3;
        if (n < NCHUNK) issue_loads(n);
        else            CP_COMMIT();

        uint32_t Ab = sb + (c % STAGES) * STAGEB + OFF_A8;
        uint32_t Bb = sb + (c % STAGES) * STAGEB + OFF_B;

#pragma unroll
        for (int gg = 0; gg < 2; gg++) {       // this warp's k32 groups
            int g = wk * 2 + gg;
            // A fragments (both mt, both k16 halves of the k32 group)
            uint32_t af[2][2][4];
#pragma unroll
            for (int mt = 0; mt < 2; mt++) {
                int r = wm * 32 + mt * 16 + a_row_off;
                int ch = 2 * g + a_ch_off;
                uint32_t t4[4];
                ldsm4(t4, Ab + (uint32_t)(r * 128 + ((ch ^ (r & 7)) << 4)));
                f8x4_to_f16x4(t4[0], af[mt][0][0], af[mt][0][2]);
                f8x4_to_f16x4(t4[1], af[mt][0][1], af[mt][0][3]);
                f8x4_to_f16x4(t4[2], af[mt][1][0], af[mt][1][2]);
                f8x4_to_f16x4(t4[3], af[mt][1][1], af[mt][1][3]);
            }
#pragma unroll
            for (int h = 0; h < 2; h++) {
                int kk = 2 * g + h;
                uint32_t bf[4][2];
#pragma unroll
                for (int cp = 0; cp < 2; cp++) {
                    int k = kk * 16 + bk_base;
                    int cn = wn * 4 + cp * 2 + bc_add;
                    uint32_t t4[4];
                    ldsm4t(t4, Bb + (uint32_t)(k * 256 + ((cn ^ (k & 7)) << 4)));
                    bf[cp * 2 + 0][0] = t4[0]; bf[cp * 2 + 0][1] = t4[1];
                    bf[cp * 2 + 1][0] = t4[2]; bf[cp * 2 + 1][1] = t4[3];
                }
#pragma unroll
                for (int mt = 0; mt < 2; mt++)
#pragma unroll
                    for (int nt = 0; nt < 4; nt++)
                        mma16816(acc[mt][nt], af[mt][h], bf[nt]);
            }
        }

        if (c + 1 < NCHUNK) CP_WAIT2();
        __syncthreads();
    }

    // ---- merge k-half partial accumulators (|Hp|^2 is nonlinear) ----
    float* mbuf = (float*)smem;
    if (wk == 1) {
        float* dst = mbuf + w8 * 1024 + lane;
        int idx = 0;
#pragma unroll
        for (int mt = 0; mt < 2; mt++)
#pragma unroll
            for (int nt = 0; nt < 4; nt++)
#pragma unroll
                for (int q = 0; q < 4; q++) dst[(idx++) * 32] = acc[mt][nt][q];
    }
    __syncthreads();
    if (wk == 0) {
        const float* src = mbuf + w8 * 1024 + lane;
        int idx = 0;
#pragma unroll
        for (int mt = 0; mt < 2; mt++)
#pragma unroll
            for (int nt = 0; nt < 4; nt++)
#pragma unroll
                for (int q = 0; q < 4; q++) acc[mt][nt][q] += src[(idx++) * 32];

        // ---- epilogue: per-row num = <H, acc>, sq = |acc|^2 ----
#pragma unroll
        for (int mt = 0; mt < 2; mt++) {
#pragma unroll
            for (int half = 0; half < 2; half++) {
                int rl = wm * 32 + mt * 16 + half * 8 + (lane >> 2);
                long long gi = bi + rl;
                float num = 0.f, sq = 0.f;
#pragma unroll
                for (int nt = 0; nt < 4; nt++) {
                    int col = wn * 32 + nt * 8 + (lane & 3) * 2;
                    float v0 = acc[mt][nt][half * 2 + 0];
                    float v1 = acc[mt][nt][half * 2 + 1];
                    float h0 = H[gi * DEMB + col];
                    float h1 = H[gi * DEMB + col + 1];
                    num += h0 * v0 + h1 * v1;
                    sq  += v0 * v0 + v1 * v1;
                }
                num += __shfl_xor_sync(~0u, num, 1);
                num += __shfl_xor_sync(~0u, num, 2);
                sq  += __shfl_xor_sync(~0u, sq, 1);
                sq  += __shfl_xor_sync(~0u, sq, 2);
                if ((lane & 3) == 0) {
                    atomicAdd(&s_num[rl], num);
                    atomicAdd(&s_sq[rl], sq);
                }
            }
        }
    }
    __syncthreads();

    if (tid < MBLK) {
        long long gi = bi + tid;
        const float4* hb = (const float4*)(H + gi * DEMB);
        float hsq = 0.f;
#pragma unroll
        for (int q = 0; q < 32; q++) {
            float4 h = hb[q];
            hsq += h.x * h.x + h.y * h.y + h.z * h.z + h.w * h.w;
        }
        float num = s_num[tid] * (1.0f / HS_SCALE);
        float sq  = s_sq[tid]  * (1.0f / (HS_SCALE * HS_SCALE));
        float dv  = g_dinv[gi];
        float den = fmaxf(sqrtf(hsq) * (dv * sqrtf(sq)), FEPS);
        float cosv = dv * num / den;
        float val = softplusf(-cosv);
#pragma unroll
        for (int o = 16; o; o >>= 1) val += __shfl_xor_sync(~0u, val, o);
        if ((tid & 31) == 0) atomicAdd(&g_Lc, val);
    }
}

__global__ __launch_bounds__(512, 1)
void mega3_kernel(const float* __restrict__ H, const int* __restrict__ rE, int nR) {
    extern __shared__ char smem[];
    if (blockIdx.x < 128) gemm_block(H, smem);
    else                  lp_block(blockIdx.x - 128, rE, nR);
}

// ---------------- finalize --------------------------------------------------
__global__ void final_kernel(float* __restrict__ out, int nU) {
    float L_u = g_Lu / (float)nU;
    float L_p = g_LpNum / fmaxf(g_LpDen, 1.f);
    float L_c = g_Lc / (float)NA;
    out[0] = L_u + L_p + 0.01f * L_c;
    out[1] = L_u;
    out[2] = L_p;
    out[3] = L_c;
}

// ---------------- launch ----------------------------------------------------
extern "C" void kernel_launch(void* const* d_in, const int* in_sizes, int n_in,
                              void* d_out, int out_size) {
    const float* pred = (const float*)d_in[0];
    const float* embO = (const float*)d_in[1];
    const float* embN = (const float*)d_in[2];
    const float* A    = (const float*)d_in[3];
    const float* H    = (const float*)d_in[4];
    const int*   uE   = (const int*)d_in[5];
    const int*   rE   = (const int*)d_in[6];
    const void*  mask = d_in[7];
    int nU = in_sizes[5] / 2;
    int nR = in_sizes[6] / 2;

    cudaFuncSetAttribute(mega3_kernel,
                         cudaFuncAttributeMaxDynamicSharedMemorySize, GEMM_SMEM);

    init_kernel<<<(NEMB + 255) / 256, 256>>>((const unsigned*)mask);
    mega1_kernel<<<NA + 16 + 1024, 256>>>((const float4*)A, mask, pred,
                                          embO, embN, uE, nU, rE, nR);
    mega2_kernel<<<32 + 1024, 256>>>(rE, nR, (const float4*)H);
    mega3_kernel<<<128 + 16, 512, GEMM_SMEM>>>(H, rE, nR);
    final_kernel<<<1, 1>>>((float*)d_out, nU);
}

// round 12
// speedup vs baseline: 1.2830x; 1.0082x over previous
#include <cuda_runtime.h>
#include <cuda_bf16.h>
#include <cuda_fp16.h>
#include <math.h>
#include <stdint.h>

#define NEMB 20000
#define DEMB 128
#define NA   8192
#define PDIM 10000
#define FEPS 1e-8f
#define HS_SCALE 64.0f

// ---------------- scratch (device globals; no allocation allowed) ----------
__device__ float    g_sims_o[NA];
__device__ float    g_sims_n[NA];
__device__ unsigned g_mkey_o[NEMB];
__device__ unsigned g_mkey_n[NEMB];
__device__ float    g_ssum_o[NEMB];
__device__ float    g_ssum_n[NEMB];
__device__ float    g_cnt[NEMB];
__device__ float    g_dinv[NA];
__device__ float    g_Lu, g_LpNum, g_LpDen, g_Lc;
__device__ int      g_mask_mode;   // 0 = byte(bool), 1 = int32, 2 = float32

// W = e4m3(A * mask) (64 MB), Ht8[d][j] = e4m3(HS_SCALE*dinv_j*H[j][d]) (1 MB)
__device__ unsigned char g_W8[(size_t)NA * NA];
__device__ unsigned char g_Ht8[(size_t)DEMB * NA];

// ---------------- helpers ---------------------------------------------------
__device__ __forceinline__ unsigned fkey(float f) {
    unsigned u = __float_as_uint(f);
    return (u & 0x80000000u) ? ~u : (u | 0x80000000u);
}
__device__ __forceinline__ float fkey_inv(unsigned k) {
    return (k & 0x80000000u) ? __uint_as_float(k & 0x7fffffffu)
                             : __uint_as_float(~k);
}
__device__ __forceinline__ float4 mask4(const void* m, int mode, int idx4) {
    float4 r;
    if (mode == 0) {                       // packed bytes (bool)
        unsigned w = __ldcs(&((const unsigned*)m)[idx4]);
        r.x = (w & 0x000000ffu) ? 1.f : 0.f;
        r.y = (w & 0x0000ff00u) ? 1.f : 0.f;
        r.z = (w & 0x00ff0000u) ? 1.f : 0.f;
        r.w = (w & 0xff000000u) ? 1.f : 0.f;
    } else if (mode == 1) {                // int32 0/1
        int4 v = __ldcs(&((const int4*)m)[idx4]);
        r.x = v.x ? 1.f : 0.f; r.y = v.y ? 1.f : 0.f;
        r.z = v.z ? 1.f : 0.f; r.w = v.w ? 1.f : 0.f;
    } else {                               // float32
        r = __ldcs(&((const float4*)m)[idx4]);
    }
    return r;
}
__device__ __forceinline__ float softplusf(float x) {
    return fmaxf(x, 0.f) + log1pf(expf(-fabsf(x)));
}
__device__ __forceinline__ uint32_t s2u(const void* p) {
    uint32_t a;
    asm("{ .reg .u64 t; cvta.to.shared.u64 t, %1; cvt.u32.u64 %0, t; }"
        : "=r"(a) : "l"(p));
    return a;
}
__device__ __forceinline__ void cp16(uint32_t dst, const void* src) {
    asm volatile("cp.async.cg.shared.global [%0], [%1], 16;\n"
                 :: "r"(dst), "l"(src) : "memory");
}
#define CP_COMMIT() asm volatile("cp.async.commit_group;" ::: "memory")
#define CP_WAIT2()  asm volatile("cp.async.wait_group 2;" ::: "memory")

__device__ __forceinline__ void ldsm4(uint32_t* r, uint32_t addr) {
    asm volatile("ldmatrix.sync.aligned.m8n8.x4.shared.b16 {%0,%1,%2,%3}, [%4];"
                 : "=r"(r[0]), "=r"(r[1]), "=r"(r[2]), "=r"(r[3]) : "r"(addr));
}
__device__ __forceinline__ void mma16816(float* c, const uint32_t* a, const uint32_t* b) {
    asm volatile(
        "mma.sync.aligned.m16n8k16.row.col.f32.f16.f16.f32 "
        "{%0,%1,%2,%3}, {%4,%5,%6,%7}, {%8,%9}, {%0,%1,%2,%3};"
        : "+f"(c[0]), "+f"(c[1]), "+f"(c[2]), "+f"(c[3])
        : "r"(a[0]), "r"(a[1]), "r"(a[2]), "r"(a[3]), "r"(b[0]), "r"(b[1]));
}
// pack 4 floats -> 4 e4m3 bytes (x0 at lowest byte)
__device__ __forceinline__ uint32_t e4m3x4(float x0, float x1, float x2, float x3) {
    uint16_t lo, hi;
    asm("cvt.rn.satfinite.e4m3x2.f32 %0, %1, %2;" : "=h"(lo) : "f"(x1), "f"(x0));
    asm("cvt.rn.satfinite.e4m3x2.f32 %0, %1, %2;" : "=h"(hi) : "f"(x3), "f"(x2));
    return (uint32_t)lo | ((uint32_t)hi << 16);
}
// 4 packed e4m3 -> two f16x2 regs (elementwise, lo->lo)
__device__ __forceinline__ void f8x4_to_f16x4(uint32_t w, uint32_t& lo, uint32_t& hi) {
    uint16_t a, b;
    asm("mov.b32 {%0,%1}, %2;" : "=h"(a), "=h"(b) : "r"(w));
    asm("cvt.rn.f16x2.e4m3x2 %0, %1;" : "=r"(lo) : "h"(a));
    asm("cvt.rn.f16x2.e4m3x2 %0, %1;" : "=r"(hi) : "h"(b));
}

// ---------------- K1: init + mask dtype detection ---------------------------
__global__ void init_kernel(const unsigned* __restrict__ m) {
    int i = blockIdx.x * blockDim.x + threadIdx.x;
    if (i < NEMB) {
        g_mkey_o[i] = 0u; g_mkey_n[i] = 0u;
        g_ssum_o[i] = 0.f; g_ssum_n[i] = 0.f;
        g_cnt[i] = 0.f;
    }
    if (i == 0) { g_Lu = 0.f; g_LpNum = 0.f; g_LpDen = 0.f; g_Lc = 0.f; }
    if (blockIdx.x == 0 && threadIdx.x < 32) {
        int vi = 0, vf = 0, vb = 0;
        for (int k = threadIdx.x; k < 256; k += 32) {
            unsigned w = m[k];
            if (w == 1u) vi++;
            else if (w == 0x3f800000u) vf++;
            else if (w != 0u) vb++;
        }
#pragma unroll
        for (int o = 16; o; o >>= 1) {
            vi += __shfl_xor_sync(~0u, vi, o);
            vf += __shfl_xor_sync(~0u, vf, o);
            vb += __shfl_xor_sync(~0u, vb, o);
        }
        if (threadIdx.x == 0) {
            int mode;
            if (vb >= vi && vb >= vf) mode = 0;
            else if (vi >= vf)        mode = 1;
            else                      mode = 2;
            g_mask_mode = mode;
        }
    }
}

// ---------------- K2 pieces -------------------------------------------------
__device__ __forceinline__ void deg_cvt_block(int row, const float4* __restrict__ A4,
                                              const void* __restrict__ mask) {
    int mode = g_mask_mode;
    int base4 = row * (NA / 4);
    unsigned* __restrict__ W4 = (unsigned*)g_W8;    // 4 fp8 per unsigned
    float s = 0.f;
#pragma unroll 4
    for (int c = threadIdx.x; c < NA / 4; c += 256) {
        float4 a = __ldcs(&A4[base4 + c]);
        float4 m = mask4(mask, mode, base4 + c);
        float x0 = a.x * m.x, x1 = a.y * m.y, x2 = a.z * m.z, x3 = a.w * m.w;
        s += (x0 + x1) + (x2 + x3);
        W4[base4 + c] = e4m3x4(x0, x1, x2, x3);
    }
    __shared__ float red[8];
#pragma unroll
    for (int o = 16; o; o >>= 1) s += __shfl_xor_sync(~0u, s, o);
    if ((threadIdx.x & 31) == 0) red[threadIdx.x >> 5] = s;
    __syncthreads();
    if (threadIdx.x < 8) {
        float v = red[threadIdx.x];
#pragma unroll
        for (int o = 4; o; o >>= 1) v += __shfl_xor_sync(0xffu, v, o);
        if (threadIdx.x == 0) g_dinv[row] = rsqrtf(v + FEPS);
    }
}

__device__ __forceinline__ void lu_block(int blk, const float* __restrict__ pred,
                                         const int* __restrict__ edges, int nE) {
    int e = blk * 256 + threadIdx.x;
    if (e >= nE) return;
    int u = edges[2 * e], v = edges[2 * e + 1];
    float s = __ldg(&pred[(long long)u * PDIM + v]);
    atomicAdd(&g_Lu, softplusf(s));
}

__device__ __forceinline__ void sims_block(int blk, const float* __restrict__ embO,
                                           const float* __restrict__ embN,
                                           const int* __restrict__ edges, int nE) {
    int warp = (blk * 256 + threadIdx.x) >> 5;
    int lane = threadIdx.x & 31;
    if (warp >= nE) return;
    int u = edges[2 * warp], v = edges[2 * warp + 1];
    const float4* uo = (const float4*)(embO + (long long)u * DEMB);
    const float4* vo = (const float4*)(embO + (long long)v * DEMB);
    const float4* un = (const float4*)(embN + (long long)u * DEMB);
    const float4* vn = (const float4*)(embN + (long long)v * DEMB);
    float4 a = uo[lane], b = vo[lane];
    float4 c = un[lane], d4 = vn[lane];
    float so = a.x * b.x + a.y * b.y + a.z * b.z + a.w * b.w;
    float sn = c.x * d4.x + c.y * d4.y + c.z * d4.z + c.w * d4.w;
#pragma unroll
    for (int o = 16; o; o >>= 1) {
        so += __shfl_xor_sync(~0u, so, o);
        sn += __shfl_xor_sync(~0u, sn, o);
    }
    if (lane == 0) {
        g_sims_o[warp] = so;
        g_sims_n[warp] = sn;
        atomicMax(&g_mkey_o[u], fkey(so));
        atomicMax(&g_mkey_n[u], fkey(sn));
    }
}

// K2: blocks [0,8192) deg rows | [8192,8208) lu | [8208,9232) sims
__global__ __launch_bounds__(256)
void mega1_kernel(const float4* __restrict__ A4, const void* __restrict__ mask,
                  const float* __restrict__ pred,
                  const float* __restrict__ embO, const float* __restrict__ embN,
                  const int* __restrict__ uE, int nU,
                  const int* __restrict__ rE, int nR) {
    int b = blockIdx.x;
    if (b < NA)            deg_cvt_block(b, A4, mask);
    else if (b < NA + 16)  lu_block(b - NA, pred, uE, nU);
    else                   sims_block(b - NA - 16, embO, embN, rE, nR);
}

// ---------------- K3: segsum + H transpose to fp8 ---------------------------
__device__ __forceinline__ void segsum_block(int blk, const int* __restrict__ edges, int nE) {
    int e = blk * 256 + threadIdx.x;
    if (e >= nE) return;
    int u = edges[2 * e];
    float mo = fkey_inv(g_mkey_o[u]);
    float mn = fkey_inv(g_mkey_n[u]);
    atomicAdd(&g_ssum_o[u], expf(g_sims_o[e] - mo));
    atomicAdd(&g_ssum_n[u], expf(g_sims_n[e] - mn));
    atomicAdd(&g_cnt[u], 1.f);
}

// Ht8[d][j] = e4m3(HS_SCALE * dinv_j * H[j][d]); block handles 64 j
__device__ void htrans_block(int blk, const float* __restrict__ H) {
    __shared__ unsigned char T[DEMB][64];     // 8KB
    int j0 = blk * 64;
    int tid = threadIdx.x;
    {
        int jl = tid >> 2;                    // 0..63
        int dg = (tid & 3) * 32;              // 0,32,64,96
        int j = j0 + jl;
        float dv = g_dinv[j] * HS_SCALE;
        const float4* hb = (const float4*)(H + (long long)j * DEMB + dg);
#pragma unroll
        for (int q = 0; q < 8; q++) {
            float4 h = hb[q];
            uint32_t u = e4m3x4(h.x * dv, h.y * dv, h.z * dv, h.w * dv);
            int d = dg + q * 4;
            T[d + 0][jl] = (unsigned char)(u);
            T[d + 1][jl] = (unsigned char)(u >> 8);
            T[d + 2][jl] = (unsigned char)(u >> 16);
            T[d + 3][jl] = (unsigned char)(u >> 24);
        }
    }
    __syncthreads();
    {
        int d = tid >> 1;
        int half = tid & 1;
        uint2 v = *(const uint2*)&T[d][half * 32];
        uint2 w = *(const uint2*)&T[d][half * 32 + 8];
        uint2 x = *(const uint2*)&T[d][half * 32 + 16];
        uint2 y = *(const uint2*)&T[d][half * 32 + 24];
        uint4 o1 = make_uint4(v.x, v.y, w.x, w.y);
        uint4 o2 = make_uint4(x.x, x.y, y.x, y.y);
        *(uint4*)&g_Ht8[(long long)d * NA + j0 + half * 32]      = o1;
        *(uint4*)&g_Ht8[(long long)d * NA + j0 + half * 32 + 16] = o2;
    }
}

__global__ __launch_bounds__(256)
void mega2_kernel(const int* __restrict__ rE, int nR, const float* __restrict__ H) {
    int b = blockIdx.x;
    if (b < 32) segsum_block(b, rE, nR);
    else        htrans_block(b - 32, H);
}

// ---------------- K4: gemm (blocks 0..127) + lp (blocks 128..143) -----------
// BOTH operands fp8 in smem, converted in registers after ldmatrix.b16.
// The fp8-ldsm k-permutation is identical on A and B, so it cancels in the dot.
#define MBLK   64
#define KBLK   128
#define STAGES 4
#define NCHUNK (NA / KBLK)              // 64
#define OFF_A8  0                       // A fp8 tile 64x128  = 8192
#define OFF_B8  8192                    // B fp8 tile 128x128 = 16384
#define STAGEB  24576
#define GEMM_SMEM (STAGES * STAGEB)     // 98304

__device__ __forceinline__ void lp_block(int blk, const int* __restrict__ edges, int nE) {
    int e = blk * 512 + threadIdx.x;
    if (e >= nE) return;
    int u = edges[2 * e];
    if (g_cnt[u] <= 1.f) return;
    float mo = fkey_inv(g_mkey_o[u]);
    float lseo = logf(g_ssum_o[u] + 1e-30f) + mo;
    float lpo  = logf(expf(g_sims_o[e] - lseo) + FEPS);
    float mn = fkey_inv(g_mkey_n[u]);
    float lsen = logf(g_ssum_n[u] + 1e-30f) + mn;
    float lpn  = logf(expf(g_sims_n[e] - lsen) + FEPS);
    float d = lpn - lpo;
    atomicAdd(&g_LpNum, d * d);
    atomicAdd(&g_LpDen, 1.f);
}

__device__ void gemm_block(const float* __restrict__ H, char* smem) {
    __shared__ float s_num[MBLK], s_sq[MBLK];
    uint32_t sb = s2u(smem);
    const int tid = threadIdx.x;
    const int lane = tid & 31;
    const int wid = tid >> 5;            // 0..15
    const int wk = wid >> 3;             // k-half 0..1
    const int w8 = wid & 7;
    const int wm = w8 & 1;               // 0..1 (M)
    const int wn = w8 >> 1;              // 0..3 (N)
    const int bi = blockIdx.x * MBLK;

    if (tid < MBLK) { s_num[tid] = 0.f; s_sq[tid] = 0.f; }

    const unsigned char* __restrict__ W  = g_W8;
    const unsigned char* __restrict__ Ht = g_Ht8;

    // A fp8 cp mapping: 512 cp16 -> 1/thread
    const int a_r = tid >> 3;
    const int a_cc = tid & 7;

    auto issue_loads = [&](int n) {
        uint32_t st = sb + (n % STAGES) * STAGEB;
        long long j0 = (long long)n * KBLK;
        cp16(st + OFF_A8 + a_r * 128 + ((a_cc ^ (a_r & 7)) << 4),
             W + (long long)(bi + a_r) * NA + j0 + a_cc * 16);
#pragma unroll
        for (int q = 0; q < 2; q++) {       // B fp8: 1024 cp16 -> 2/thread
            int id = tid + q * 512;
            int d = id >> 3, ck = id & 7;
            cp16(st + OFF_B8 + d * 128 + ((ck ^ (d & 7)) << 4),
                 Ht + (long long)d * NA + j0 + ck * 16);
        }
        CP_COMMIT();
    };

    float acc[2][4][4];
#pragma unroll
    for (int mt = 0; mt < 2; mt++)
#pragma unroll
        for (int nt = 0; nt < 4; nt++)
#pragma unroll
            for (int q = 0; q < 4; q++) acc[mt][nt][q] = 0.f;

    const int grp = lane >> 3;                 // 0..3
    const int l7  = lane & 7;
    // fp8 ldsm x4 tiling: rows +8*(grp&1), chunk +(grp>>1)
    const int row_off = ((grp & 1) << 3) + l7;
    const int ch_off  = grp >> 1;

    issue_loads(0); issue_loads(1); issue_loads(2);
    CP_WAIT2();
    __syncthreads();

    for (int c = 0; c < NCHUNK; c++) {
        int n = c + 3;
        if (n < NCHUNK) issue_loads(n);
        else            CP_COMMIT();

        uint32_t Ab = sb + (c % STAGES) * STAGEB + OFF_A8;
        uint32_t Bb = sb + (c % STAGES) * STAGEB + OFF_B8;

#pragma unroll
        for (int gg = 0; gg < 2; gg++) {       // this warp's k32 groups
            int g = wk * 2 + gg;
            int ch = 2 * g + ch_off;
            // A fragments: [mt][h(k16)][4 regs]
            uint32_t af[2][2][4];
#pragma unroll
            for (int mt = 0; mt < 2; mt++) {
                int r = wm * 32 + mt * 16 + row_off;
                uint32_t t4[4];
                ldsm4(t4, Ab + (uint32_t)(r * 128 + ((ch ^ (r & 7)) << 4)));
                f8x4_to_f16x4(t4[0], af[mt][0][0], af[mt][0][2]);
                f8x4_to_f16x4(t4[1], af[mt][0][1], af[mt][0][3]);
                f8x4_to_f16x4(t4[2], af[mt][1][0], af[mt][1][2]);
                f8x4_to_f16x4(t4[3], af[mt][1][1], af[mt][1][3]);
            }
            // B fragments: [nt][h][2 regs]
            uint32_t bf[4][2][2];
#pragma unroll
            for (int p = 0; p < 2; p++) {
                int nrow = wn * 32 + p * 16 + row_off;
                uint32_t t4[4];
                ldsm4(t4, Bb + (uint32_t)(nrow * 128 + ((ch ^ (nrow & 7)) << 4)));
                f8x4_to_f16x4(t4[0], bf[2 * p + 0][0][0], bf[2 * p + 0][0][1]);
                f8x4_to_f16x4(t4[1], bf[2 * p + 1][0][0], bf[2 * p + 1][0][1]);
                f8x4_to_f16x4(t4[2], bf[2 * p + 0][1][0], bf[2 * p + 0][1][1]);
                f8x4_to_f16x4(t4[3], bf[2 * p + 1][1][0], bf[2 * p + 1][1][1]);
            }
#pragma unroll
            for (int h = 0; h < 2; h++)
#pragma unroll
                for (int mt = 0; mt < 2; mt++)
#pragma unroll
                    for (int nt = 0; nt < 4; nt++)
                        mma16816(acc[mt][nt], af[mt][h], bf[nt][h]);
        }

        if (c + 1 < NCHUNK) CP_WAIT2();
        __syncthreads();
    }

    // ---- merge k-half partial accumulators (|Hp|^2 is nonlinear) ----
    float* mbuf = (float*)smem;
    if (wk == 1) {
        float* dst = mbuf + w8 * 1024 + lane;
        int idx = 0;
#pragma unroll
        for (int mt = 0; mt < 2; mt++)
#pragma unroll
            for (int nt = 0; nt < 4; nt++)
#pragma unroll
                for (int q = 0; q < 4; q++) dst[(idx++) * 32] = acc[mt][nt][q];
    }
    __syncthreads();
    if (wk == 0) {
        const float* src = mbuf + w8 * 1024 + lane;
        int idx = 0;
#pragma unroll
        for (int mt = 0; mt < 2; mt++)
#pragma unroll
            for (int nt = 0; nt < 4; nt++)
#pragma unroll
                for (int q = 0; q < 4; q++) acc[mt][nt][q] += src[(idx++) * 32];

        // ---- epilogue: per-row num = <H, acc>, sq = |acc|^2 ----
#pragma unroll
        for (int mt = 0; mt < 2; mt++) {
#pragma unroll
            for (int half = 0; half < 2; half++) {
                int rl = wm * 32 + mt * 16 + half * 8 + (lane >> 2);
                long long gi = bi + rl;
                float num = 0.f, sq = 0.f;
#pragma unroll
                for (int nt = 0; nt < 4; nt++) {
                    int col = wn * 32 + nt * 8 + (lane & 3) * 2;
                    float v0 = acc[mt][nt][half * 2 + 0];
                    float v1 = acc[mt][nt][half * 2 + 1];
                    float h0 = H[gi * DEMB + col];
                    float h1 = H[gi * DEMB + col + 1];
                    num += h0 * v0 + h1 * v1;
                    sq  += v0 * v0 + v1 * v1;
                }
                num += __shfl_xor_sync(~0u, num, 1);
                num += __shfl_xor_sync(~0u, num, 2);
                sq  += __shfl_xor_sync(~0u, sq, 1);
                sq  += __shfl_xor_sync(~0u, sq, 2);
                if ((lane & 3) == 0) {
                    atomicAdd(&s_num[rl], num);
                    atomicAdd(&s_sq[rl], sq);
                }
            }
        }
    }
    __syncthreads();

    if (tid < MBLK) {
        long long gi = bi + tid;
        const float4* hb = (const float4*)(H + gi * DEMB);
        float hsq = 0.f;
#pragma unroll
        for (int q = 0; q < 32; q++) {
            float4 h = hb[q];
            hsq += h.x * h.x + h.y * h.y + h.z * h.z + h.w * h.w;
        }
        float num = s_num[tid] * (1.0f / HS_SCALE);
        float sq  = s_sq[tid]  * (1.0f / (HS_SCALE * HS_SCALE));
        float dv  = g_dinv[gi];
        float den = fmaxf(sqrtf(hsq) * (dv * sqrtf(sq)), FEPS);
        float cosv = dv * num / den;
        float val = softplusf(-cosv);
#pragma unroll
        for (int o = 16; o; o >>= 1) val += __shfl_xor_sync(~0u, val, o);
        if ((tid & 31) == 0) atomicAdd(&g_Lc, val);
    }
}

__global__ __launch_bounds__(512, 1)
void mega3_kernel(const float* __restrict__ H, const int* __restrict__ rE, int nR) {
    extern __shared__ char smem[];
    if (blockIdx.x < 128) gemm_block(H, smem);
    else                  lp_block(blockIdx.x - 128, rE, nR);
}

// ---------------- finalize --------------------------------------------------
__global__ void final_kernel(float* __restrict__ out, int nU) {
    float L_u = g_Lu / (float)nU;
    float L_p = g_LpNum / fmaxf(g_LpDen, 1.f);
    float L_c = g_Lc / (float)NA;
    out[0] = L_u + L_p + 0.01f * L_c;
    out[1] = L_u;
    out[2] = L_p;
    out[3] = L_c;
}

// ---------------- launch ----------------------------------------------------
extern "C" void kernel_launch(void* const* d_in, const int* in_sizes, int n_in,
                              void* d_out, int out_size) {
    const float* pred = (const float*)d_in[0];
    const float* embO = (const float*)d_in[1];
    const float* embN = (const float*)d_in[2];
    const float* A    = (const float*)d_in[3];
    const float* H    = (const float*)d_in[4];
    const int*   uE   = (const int*)d_in[5];
    const int*   rE   = (const int*)d_in[6];
    const void*  mask = d_in[7];
    int nU = in_sizes[5] / 2;
    int nR = in_sizes[6] / 2;

    cudaFuncSetAttribute(mega3_kernel,
                         cudaFuncAttributeMaxDynamicSharedMemorySize, GEMM_SMEM);

    init_kernel<<<(NEMB + 255) / 256, 256>>>((const unsigned*)mask);
    mega1_kernel<<<NA + 16 + 1024, 256>>>((const float4*)A, mask, pred,
                                          embO, embN, uE, nU, rE, nR);
    mega2_kernel<<<32 + NA / 64, 256>>>(rE, nR, H);
    mega3_kernel<<<128 + 16, 512, GEMM_SMEM>>>(H, rE, nR);
    final_kernel<<<1, 1>>>((float*)d_out, nU);
}

// round 13
// speedup vs baseline: 1.3057x; 1.0177x over previous
#include <cuda_runtime.h>
#include <cuda_bf16.h>
#include <cuda_fp16.h>
#include <math.h>
#include <stdint.h>

#define NEMB 20000
#define DEMB 128
#define NA   8192
#define PDIM 10000
#define FEPS 1e-8f
#define HS_SCALE 64.0f

// ---------------- scratch (device globals; no allocation allowed) ----------
__device__ float    g_sims_o[NA];
__device__ float    g_sims_n[NA];
__device__ unsigned g_mkey_o[NEMB];
__device__ unsigned g_mkey_n[NEMB];
__device__ float    g_ssum_o[NEMB];
__device__ float    g_ssum_n[NEMB];
__device__ float    g_cnt[NEMB];
__device__ float    g_dinv[NA];
__device__ float    g_Lu, g_LpNum, g_LpDen, g_Lc;
__device__ int      g_mask_mode;   // 0 = byte(bool), 1 = int32, 2 = float32

// W = e4m3(A * mask) (64 MB), Ht8[d][j] = e4m3(HS_SCALE*dinv_j*H[j][d]) (1 MB)
__device__ unsigned char g_W8[(size_t)NA * NA];
__device__ unsigned char g_Ht8[(size_t)DEMB * NA];

// ---------------- helpers ---------------------------------------------------
__device__ __forceinline__ unsigned fkey(float f) {
    unsigned u = __float_as_uint(f);
    return (u & 0x80000000u) ? ~u : (u | 0x80000000u);
}
__device__ __forceinline__ float fkey_inv(unsigned k) {
    return (k & 0x80000000u) ? __uint_as_float(k & 0x7fffffffu)
                             : __uint_as_float(~k);
}
__device__ __forceinline__ float4 mask4(const void* m, int mode, int idx4) {
    float4 r;
    if (mode == 0) {                       // packed bytes (bool)
        unsigned w = __ldcs(&((const unsigned*)m)[idx4]);
        r.x = (w & 0x000000ffu) ? 1.f : 0.f;
        r.y = (w & 0x0000ff00u) ? 1.f : 0.f;
        r.z = (w & 0x00ff0000u) ? 1.f : 0.f;
        r.w = (w & 0xff000000u) ? 1.f : 0.f;
    } else if (mode == 1) {                // int32 0/1
        int4 v = __ldcs(&((const int4*)m)[idx4]);
        r.x = v.x ? 1.f : 0.f; r.y = v.y ? 1.f : 0.f;
        r.z = v.z ? 1.f : 0.f; r.w = v.w ? 1.f : 0.f;
    } else {                               // float32
        r = __ldcs(&((const float4*)m)[idx4]);
    }
    return r;
}
__device__ __forceinline__ float softplusf(float x) {
    return fmaxf(x, 0.f) + log1pf(expf(-fabsf(x)));
}
__device__ __forceinline__ uint32_t s2u(const void* p) {
    uint32_t a;
    asm("{ .reg .u64 t; cvta.to.shared.u64 t, %1; cvt.u32.u64 %0, t; }"
        : "=r"(a) : "l"(p));
    return a;
}
__device__ __forceinline__ void cp16(uint32_t dst, const void* src) {
    asm volatile("cp.async.cg.shared.global [%0], [%1], 16;\n"
                 :: "r"(dst), "l"(src) : "memory");
}
#define CP_COMMIT() asm volatile("cp.async.commit_group;" ::: "memory")
#define CP_WAIT2()  asm volatile("cp.async.wait_group 2;" ::: "memory")

__device__ __forceinline__ void ldsm4(uint32_t* r, uint32_t addr) {
    asm volatile("ldmatrix.sync.aligned.m8n8.x4.shared.b16 {%0,%1,%2,%3}, [%4];"
                 : "=r"(r[0]), "=r"(r[1]), "=r"(r[2]), "=r"(r[3]) : "r"(addr));
}
__device__ __forceinline__ void mma16816(float* c, const uint32_t* a, const uint32_t* b) {
    asm volatile(
        "mma.sync.aligned.m16n8k16.row.col.f32.f16.f16.f32 "
        "{%0,%1,%2,%3}, {%4,%5,%6,%7}, {%8,%9}, {%0,%1,%2,%3};"
        : "+f"(c[0]), "+f"(c[1]), "+f"(c[2]), "+f"(c[3])
        : "r"(a[0]), "r"(a[1]), "r"(a[2]), "r"(a[3]), "r"(b[0]), "r"(b[1]));
}
// pack 4 floats -> 4 e4m3 bytes (x0 at lowest byte)
__device__ __forceinline__ uint32_t e4m3x4(float x0, float x1, float x2, float x3) {
    uint16_t lo, hi;
    asm("cvt.rn.satfinite.e4m3x2.f32 %0, %1, %2;" : "=h"(lo) : "f"(x1), "f"(x0));
    asm("cvt.rn.satfinite.e4m3x2.f32 %0, %1, %2;" : "=h"(hi) : "f"(x3), "f"(x2));
    return (uint32_t)lo | ((uint32_t)hi << 16);
}
// 4 packed e4m3 -> two f16x2 regs (elementwise, lo->lo)
__device__ __forceinline__ void f8x4_to_f16x4(uint32_t w, uint32_t& lo, uint32_t& hi) {
    uint16_t a, b;
    asm("mov.b32 {%0,%1}, %2;" : "=h"(a), "=h"(b) : "r"(w));
    asm("cvt.rn.f16x2.e4m3x2 %0, %1;" : "=r"(lo) : "h"(a));
    asm("cvt.rn.f16x2.e4m3x2 %0, %1;" : "=r"(hi) : "h"(b));
}

// ---------------- K1: init + mask dtype detection ---------------------------
__global__ void init_kernel(const unsigned* __restrict__ m) {
    int i = blockIdx.x * blockDim.x + threadIdx.x;
    if (i < NEMB) {
        g_mkey_o[i] = 0u; g_mkey_n[i] = 0u;
        g_ssum_o[i] = 0.f; g_ssum_n[i] = 0.f;
        g_cnt[i] = 0.f;
    }
    if (i == 0) { g_Lu = 0.f; g_LpNum = 0.f; g_LpDen = 0.f; g_Lc = 0.f; }
    if (blockIdx.x == 0 && threadIdx.x < 32) {
        int vi = 0, vf = 0, vb = 0;
        for (int k = threadIdx.x; k < 256; k += 32) {
            unsigned w = m[k];
            if (w == 1u) vi++;
            else if (w == 0x3f800000u) vf++;
            else if (w != 0u) vb++;
        }
#pragma unroll
        for (int o = 16; o; o >>= 1) {
            vi += __shfl_xor_sync(~0u, vi, o);
            vf += __shfl_xor_sync(~0u, vf, o);
            vb += __shfl_xor_sync(~0u, vb, o);
        }
        if (threadIdx.x == 0) {
            int mode;
            if (vb >= vi && vb >= vf) mode = 0;
            else if (vi >= vf)        mode = 1;
            else                      mode = 2;
            g_mask_mode = mode;
        }
    }
}

// ---------------- K2 pieces -------------------------------------------------
__device__ __forceinline__ void deg_cvt_block(int row, const float4* __restrict__ A4,
                                              const void* __restrict__ mask) {
    int mode = g_mask_mode;
    int base4 = row * (NA / 4);
    unsigned* __restrict__ W4 = (unsigned*)g_W8;    // 4 fp8 per unsigned
    float s = 0.f;
#pragma unroll 4
    for (int c = threadIdx.x; c < NA / 4; c += 256) {
        float4 a = __ldcs(&A4[base4 + c]);
        float4 m = mask4(mask, mode, base4 + c);
        float x0 = a.x * m.x, x1 = a.y * m.y, x2 = a.z * m.z, x3 = a.w * m.w;
        s += (x0 + x1) + (x2 + x3);
        W4[base4 + c] = e4m3x4(x0, x1, x2, x3);
    }
    __shared__ float red[8];
#pragma unroll
    for (int o = 16; o; o >>= 1) s += __shfl_xor_sync(~0u, s, o);
    if ((threadIdx.x & 31) == 0) red[threadIdx.x >> 5] = s;
    __syncthreads();
    if (threadIdx.x < 8) {
        float v = red[threadIdx.x];
#pragma unroll
        for (int o = 4; o; o >>= 1) v += __shfl_xor_sync(0xffu, v, o);
        if (threadIdx.x == 0) g_dinv[row] = rsqrtf(v + FEPS);
    }
}

__device__ __forceinline__ void lu_block(int blk, const float* __restrict__ pred,
                                         const int* __restrict__ edges, int nE) {
    int e = blk * 256 + threadIdx.x;
    if (e >= nE) return;
    int u = edges[2 * e], v = edges[2 * e + 1];
    float s = __ldg(&pred[(long long)u * PDIM + v]);
    atomicAdd(&g_Lu, softplusf(s));
}

__device__ __forceinline__ void sims_block(int blk, const float* __restrict__ embO,
                                           const float* __restrict__ embN,
                                           const int* __restrict__ edges, int nE) {
    int warp = (blk * 256 + threadIdx.x) >> 5;
    int lane = threadIdx.x & 31;
    if (warp >= nE) return;
    int u = edges[2 * warp], v = edges[2 * warp + 1];
    const float4* uo = (const float4*)(embO + (long long)u * DEMB);
    const float4* vo = (const float4*)(embO + (long long)v * DEMB);
    const float4* un = (const float4*)(embN + (long long)u * DEMB);
    const float4* vn = (const float4*)(embN + (long long)v * DEMB);
    float4 a = uo[lane], b = vo[lane];
    float4 c = un[lane], d4 = vn[lane];
    float so = a.x * b.x + a.y * b.y + a.z * b.z + a.w * b.w;
    float sn = c.x * d4.x + c.y * d4.y + c.z * d4.z + c.w * d4.w;
#pragma unroll
    for (int o = 16; o; o >>= 1) {
        so += __shfl_xor_sync(~0u, so, o);
        sn += __shfl_xor_sync(~0u, sn, o);
    }
    if (lane == 0) {
        g_sims_o[warp] = so;
        g_sims_n[warp] = sn;
        atomicMax(&g_mkey_o[u], fkey(so));
        atomicMax(&g_mkey_n[u], fkey(sn));
    }
}

// K2: blocks [0,8192) deg rows | [8192,8208) lu | [8208,9232) sims
__global__ __launch_bounds__(256)
void mega1_kernel(const float4* __restrict__ A4, const void* __restrict__ mask,
                  const float* __restrict__ pred,
                  const float* __restrict__ embO, const float* __restrict__ embN,
                  const int* __restrict__ uE, int nU,
                  const int* __restrict__ rE, int nR) {
    int b = blockIdx.x;
    if (b < NA)            deg_cvt_block(b, A4, mask);
    else if (b < NA + 16)  lu_block(b - NA, pred, uE, nU);
    else                   sims_block(b - NA - 16, embO, embN, rE, nR);
}

// ---------------- K3: segsum + H transpose to fp8 ---------------------------
__device__ __forceinline__ void segsum_block(int blk, const int* __restrict__ edges, int nE) {
    int e = blk * 256 + threadIdx.x;
    if (e >= nE) return;
    int u = edges[2 * e];
    float mo = fkey_inv(g_mkey_o[u]);
    float mn = fkey_inv(g_mkey_n[u]);
    atomicAdd(&g_ssum_o[u], expf(g_sims_o[e] - mo));
    atomicAdd(&g_ssum_n[u], expf(g_sims_n[e] - mn));
    atomicAdd(&g_cnt[u], 1.f);
}

// Ht8[d][j] = e4m3(HS_SCALE * dinv_j * H[j][d]); block handles 64 j
__device__ void htrans_block(int blk, const float* __restrict__ H) {
    __shared__ unsigned char T[DEMB][64];     // 8KB
    int j0 = blk * 64;
    int tid = threadIdx.x;
    {
        int jl = tid >> 2;                    // 0..63
        int dg = (tid & 3) * 32;              // 0,32,64,96
        int j = j0 + jl;
        float dv = g_dinv[j] * HS_SCALE;
        const float4* hb = (const float4*)(H + (long long)j * DEMB + dg);
#pragma unroll
        for (int q = 0; q < 8; q++) {
            float4 h = hb[q];
            uint32_t u = e4m3x4(h.x * dv, h.y * dv, h.z * dv, h.w * dv);
            int d = dg + q * 4;
            T[d + 0][jl] = (unsigned char)(u);
            T[d + 1][jl] = (unsigned char)(u >> 8);
            T[d + 2][jl] = (unsigned char)(u >> 16);
            T[d + 3][jl] = (unsigned char)(u >> 24);
        }
    }
    __syncthreads();
    {
        int d = tid >> 1;
        int half = tid & 1;
        uint2 v = *(const uint2*)&T[d][half * 32];
        uint2 w = *(const uint2*)&T[d][half * 32 + 8];
        uint2 x = *(const uint2*)&T[d][half * 32 + 16];
        uint2 y = *(const uint2*)&T[d][half * 32 + 24];
        uint4 o1 = make_uint4(v.x, v.y, w.x, w.y);
        uint4 o2 = make_uint4(x.x, x.y, y.x, y.y);
        *(uint4*)&g_Ht8[(long long)d * NA + j0 + half * 32]      = o1;
        *(uint4*)&g_Ht8[(long long)d * NA + j0 + half * 32 + 16] = o2;
    }
}

__global__ __launch_bounds__(256)
void mega2_kernel(const int* __restrict__ rE, int nR, const float* __restrict__ H) {
    int b = blockIdx.x;
    if (b < 32) segsum_block(b, rE, nR);
    else        htrans_block(b - 32, H);
}

// ---------------- K4: gemm (blocks 0..127) + lp (blocks 128..143) -----------
// BOTH operands fp8 in smem, converted in registers after ldmatrix.b16.
// The fp8-ldsm k-permutation is identical on A and B, so it cancels in the dot.
#define MBLK   64
#define KBLK   128
#define STAGES 4
#define NCHUNK (NA / KBLK)              // 64
#define OFF_A8  0                       // A fp8 tile 64x128  = 8192
#define OFF_B8  8192                    // B fp8 tile 128x128 = 16384
#define STAGEB  24576
#define GEMM_SMEM (STAGES * STAGEB)     // 98304

__device__ __forceinline__ void lp_block(int blk, const int* __restrict__ edges, int nE) {
    int e = blk * 512 + threadIdx.x;
    if (e >= nE) return;
    int u = edges[2 * e];
    if (g_cnt[u] <= 1.f) return;
    float mo = fkey_inv(g_mkey_o[u]);
    float lseo = logf(g_ssum_o[u] + 1e-30f) + mo;
    float lpo  = logf(expf(g_sims_o[e] - lseo) + FEPS);
    float mn = fkey_inv(g_mkey_n[u]);
    float lsen = logf(g_ssum_n[u] + 1e-30f) + mn;
    float lpn  = logf(expf(g_sims_n[e] - lsen) + FEPS);
    float d = lpn - lpo;
    atomicAdd(&g_LpNum, d * d);
    atomicAdd(&g_LpDen, 1.f);
}

__device__ void gemm_block(const float* __restrict__ H, char* smem) {
    __shared__ float s_num[MBLK], s_sq[MBLK];
    uint32_t sb = s2u(smem);
    const int tid = threadIdx.x;
    const int lane = tid & 31;
    const int wid = tid >> 5;            // 0..15
    const int wk = wid >> 3;             // k-half 0..1
    const int w8 = wid & 7;
    const int wm = w8 & 1;               // 0..1 (M)
    const int wn = w8 >> 1;              // 0..3 (N)
    const int bi = blockIdx.x * MBLK;

    if (tid < MBLK) { s_num[tid] = 0.f; s_sq[tid] = 0.f; }

    const unsigned char* __restrict__ W  = g_W8;
    const unsigned char* __restrict__ Ht = g_Ht8;

    // A fp8 cp mapping: 512 cp16 -> 1/thread
    const int a_r = tid >> 3;
    const int a_cc = tid & 7;

    auto issue_loads = [&](int n) {
        uint32_t st = sb + (n % STAGES) * STAGEB;
        long long j0 = (long long)n * KBLK;
        cp16(st + OFF_A8 + a_r * 128 + ((a_cc ^ (a_r & 7)) << 4),
             W + (long long)(bi + a_r) * NA + j0 + a_cc * 16);
#pragma unroll
        for (int q = 0; q < 2; q++) {       // B fp8: 1024 cp16 -> 2/thread
            int id = tid + q * 512;
            int d = id >> 3, ck = id & 7;
            cp16(st + OFF_B8 + d * 128 + ((ck ^ (d & 7)) << 4),
                 Ht + (long long)d * NA + j0 + ck * 16);
        }
        CP_COMMIT();
    };

    float acc[2][4][4];
#pragma unroll
    for (int mt = 0; mt < 2; mt++)
#pragma unroll
        for (int nt = 0; nt < 4; nt++)
#pragma unroll
            for (int q = 0; q < 4; q++) acc[mt][nt][q] = 0.f;

    const int grp = lane >> 3;                 // 0..3
    const int l7  = lane & 7;
    // fp8 ldsm x4 tiling: rows +8*(grp&1), chunk +(grp>>1)
    const int row_off = ((grp & 1) << 3) + l7;
    const int ch_off  = grp >> 1;

    issue_loads(0); issue_loads(1); issue_loads(2);
    CP_WAIT2();
    __syncthreads();

    for (int c = 0; c < NCHUNK; c++) {
        int n = c + 3;
        if (n < NCHUNK) issue_loads(n);
        else            CP_COMMIT();

        uint32_t Ab = sb + (c % STAGES) * STAGEB + OFF_A8;
        uint32_t Bb = sb + (c % STAGES) * STAGEB + OFF_B8;

#pragma unroll
        for (int gg = 0; gg < 2; gg++) {       // this warp's k32 groups
            int g = wk * 2 + gg;
            int ch = 2 * g + ch_off;
            // A fragments: [mt][h(k16)][4 regs]
            uint32_t af[2][2][4];
#pragma unroll
            for (int mt = 0; mt < 2; mt++) {
                int r = wm * 32 + mt * 16 + row_off;
                uint32_t t4[4];
                ldsm4(t4, Ab + (uint32_t)(r * 128 + ((ch ^ (r & 7)) << 4)));
                f8x4_to_f16x4(t4[0], af[mt][0][0], af[mt][0][2]);
                f8x4_to_f16x4(t4[1], af[mt][0][1], af[mt][0][3]);
                f8x4_to_f16x4(t4[2], af[mt][1][0], af[mt][1][2]);
                f8x4_to_f16x4(t4[3], af[mt][1][1], af[mt][1][3]);
            }
            // B fragments: [nt][h][2 regs]
            uint32_t bf[4][2][2];
#pragma unroll
            for (int p = 0; p < 2; p++) {
                int nrow = wn * 32 + p * 16 + row_off;
                uint32_t t4[4];
                ldsm4(t4, Bb + (uint32_t)(nrow * 128 + ((ch ^ (nrow & 7)) << 4)));
                f8x4_to_f16x4(t4[0], bf[2 * p + 0][0][0], bf[2 * p + 0][0][1]);
                f8x4_to_f16x4(t4[1], bf[2 * p + 1][0][0], bf[2 * p + 1][0][1]);
                f8x4_to_f16x4(t4[2], bf[2 * p + 0][1][0], bf[2 * p + 0][1][1]);
                f8x4_to_f16x4(t4[3], bf[2 * p + 1][1][0], bf[2 * p + 1][1][1]);
            }
#pragma unroll
            for (int h = 0; h < 2; h++)
#pragma unroll
                for (int mt = 0; mt < 2; mt++)
#pragma unroll
                    for (int nt = 0; nt < 4; nt++)
                        mma16816(acc[mt][nt], af[mt][h], bf[nt][h]);
        }

        if (c + 1 < NCHUNK) CP_WAIT2();
        __syncthreads();
    }

    // ---- merge k-half partial accumulators (|Hp|^2 is nonlinear) ----
    float* mbuf = (float*)smem;
    if (wk == 1) {
        float* dst = mbuf + w8 * 1024 + lane;
        int idx = 0;
#pragma unroll
        for (int mt = 0; mt < 2; mt++)
#pragma unroll
            for (int nt = 0; nt < 4; nt++)
#pragma unroll
                for (int q = 0; q < 4; q++) dst[(idx++) * 32] = acc[mt][nt][q];
    }
    __syncthreads();
    if (wk == 0) {
        const float* src = mbuf + w8 * 1024 + lane;
        int idx = 0;
#pragma unroll
        for (int mt = 0; mt < 2; mt++)
#pragma unroll
            for (int nt = 0; nt < 4; nt++)
#pragma unroll
                for (int q = 0; q < 4; q++) acc[mt][nt][q] += src[(idx++) * 32];

        // ---- epilogue: per-row num = <H, acc>, sq = |acc|^2 ----
#pragma unroll
        for (int mt = 0; mt < 2; mt++) {
#pragma unroll
            for (int half = 0; half < 2; half++) {
                int rl = wm * 32 + mt * 16 + half * 8 + (lane >> 2);
                long long gi = bi + rl;
                float num = 0.f, sq = 0.f;
#pragma unroll
                for (int nt = 0; nt < 4; nt++) {
                    int col = wn * 32 + nt * 8 + (lane & 3) * 2;
                    float v0 = acc[mt][nt][half * 2 + 0];
                    float v1 = acc[mt][nt][half * 2 + 1];
                    float h0 = H[gi * DEMB + col];
                    float h1 = H[gi * DEMB + col + 1];
                    num += h0 * v0 + h1 * v1;
                    sq  += v0 * v0 + v1 * v1;
                }
                num += __shfl_xor_sync(~0u, num, 1);
                num += __shfl_xor_sync(~0u, num, 2);
                sq  += __shfl_xor_sync(~0u, sq, 1);
                sq  += __shfl_xor_sync(~0u, sq, 2);
                if ((lane & 3) == 0) {
                    atomicAdd(&s_num[rl], num);
                    atomicAdd(&s_sq[rl], sq);
                }
            }
        }
    }
    __syncthreads();

    if (tid < MBLK) {
        long long gi = bi + tid;
        const float4* hb = (const float4*)(H + gi * DEMB);
        float hsq = 0.f;
#pragma unroll
        for (int q = 0; q < 32; q++) {
            float4 h = hb[q];
            hsq += h.x * h.x + h.y * h.y + h.z * h.z + h.w * h.w;
        }
        float num = s_num[tid] * (1.0f / HS_SCALE);
        float sq  = s_sq[tid]  * (1.0f / (HS_SCALE * HS_SCALE));
        float dv  = g_dinv[gi];
        float den = fmaxf(sqrtf(hsq) * (dv * sqrtf(sq)), FEPS);
        float cosv = dv * num / den;
        float val = softplusf(-cosv);
#pragma unroll
        for (int o = 16; o; o >>= 1) val += __shfl_xor_sync(~0u, val, o);
        if ((tid & 31) == 0) atomicAdd(&g_Lc, val);
    }
}

__global__ __launch_bounds__(512, 1)
void mega3_kernel(const float* __restrict__ H, const int* __restrict__ rE, int nR) {
    extern __shared__ char smem[];
    if (blockIdx.x < 128) gemm_block(H, smem);
    else                  lp_block(blockIdx.x - 128, rE, nR);
}

// ---------------- finalize --------------------------------------------------
__global__ void final_kernel(float* __restrict__ out, int nU) {
    float L_u = g_Lu / (float)nU;
    float L_p = g_LpNum / fmaxf(g_LpDen, 1.f);
    float L_c = g_Lc / (float)NA;
    out[0] = L_u + L_p + 0.01f * L_c;
    out[1] = L_u;
    out[2] = L_p;
    out[3] = L_c;
}

// ---------------- launch ----------------------------------------------------
extern "C" void kernel_launch(void* const* d_in, const int* in_sizes, int n_in,
                              void* d_out, int out_size) {
    const float* pred = (const float*)d_in[0];
    const float* embO = (const float*)d_in[1];
    const float* embN = (const float*)d_in[2];
    const float* A    = (const float*)d_in[3];
    const float* H    = (const float*)d_in[4];
    const int*   uE   = (const int*)d_in[5];
    const int*   rE   = (const int*)d_in[6];
    const void*  mask = d_in[7];
    int nU = in_sizes[5] / 2;
    int nR = in_sizes[6] / 2;

    cudaFuncSetAttribute(mega3_kernel,
                         cudaFuncAttributeMaxDynamicSharedMemorySize, GEMM_SMEM);

    init_kernel<<<(NEMB + 255) / 256, 256>>>((const unsigned*)mask);
    mega1_kernel<<<NA + 16 + 1024, 256>>>((const float4*)A, mask, pred,
                                          embO, embN, uE, nU, rE, nR);
    mega2_kernel<<<32 + NA / 64, 256>>>(rE, nR, H);
    mega3_kernel<<<128 + 16, 512, GEMM_SMEM>>>(H, rE, nR);
    final_kernel<<<1, 1>>>((float*)d_out, nU);
}